// round 12
// baseline (speedup 1.0000x reference)
#include <cuda_runtime.h>
#include <cuda_fp16.h>
#include <math.h>
#include <stdint.h>

#define TOK   4096
#define DIM   1024
#define NEXP  8
#define EHID  2816
#define SHID  1536
#define LDH   72      // smem row stride in fp16 elems (64 data + 8 pad)

typedef __half fp16;

// ---------------- scratch (device globals) ----------------------------------
__device__ fp16  g_xh [(size_t)TOK*DIM];
__device__ fp16  g_w1h[(size_t)NEXP*EHID*DIM];
__device__ fp16  g_w3h[(size_t)NEXP*EHID*DIM];
__device__ fp16  g_w2h[(size_t)NEXP*DIM*EHID];
__device__ fp16  g_s1h[(size_t)SHID*DIM];
__device__ fp16  g_s3h[(size_t)SHID*DIM];
__device__ fp16  g_s2h[(size_t)DIM*SHID];
__device__ fp16  g_hh [(size_t)NEXP*TOK*EHID];   // routed hidden (fp16)
__device__ fp16  g_hsh[(size_t)TOK*SHID];        // shared hidden
__device__ float g_yp [(size_t)NEXP*TOK*DIM];
__device__ int   g_cnt[NEXP];
__device__ int   g_idx[NEXP*TOK];
__device__ float g_wgt[NEXP*TOK];
__device__ int   g_slot[TOK*2];

// ---------------- helpers ----------------------------------------------------
__device__ __forceinline__ uint32_t smem_u32(const void* p) {
    uint32_t a;
    asm("{ .reg .u64 t; cvta.to.shared.u64 t, %1; cvt.u32.u64 %0, t; }"
        : "=r"(a) : "l"(p));
    return a;
}
__device__ __forceinline__ void cp16(uint32_t saddr, const void* g, bool valid) {
    int sz = valid ? 16 : 0;
    asm volatile("cp.async.cg.shared.global [%0], [%1], 16, %2;"
                 :: "r"(saddr), "l"(g), "r"(sz));
}
#define CP_COMMIT() asm volatile("cp.async.commit_group;")
#define CP_WAIT1()  asm volatile("cp.async.wait_group 1;")
#define CP_WAIT0()  asm volatile("cp.async.wait_group 0;")

#define LDSM4(r, addr) \
    asm volatile("ldmatrix.sync.aligned.m8n8.x4.shared.b16 {%0,%1,%2,%3}, [%4];" \
        : "=r"((r)[0]), "=r"((r)[1]), "=r"((r)[2]), "=r"((r)[3]) : "r"(addr))

__device__ __forceinline__ void mma_f16(float d[4], const uint32_t a[4],
                                        uint32_t b0, uint32_t b1) {
    asm volatile(
        "mma.sync.aligned.m16n8k16.row.col.f32.f16.f16.f32 "
        "{%0,%1,%2,%3},{%4,%5,%6,%7},{%8,%9},{%0,%1,%2,%3};"
        : "+f"(d[0]), "+f"(d[1]), "+f"(d[2]), "+f"(d[3])
        : "r"(a[0]), "r"(a[1]), "r"(a[2]), "r"(a[3]), "r"(b0), "r"(b1));
}

__device__ __forceinline__ uint32_t pack2(fp16 a, fp16 b) {
    return ((uint32_t)__half_as_ushort(b) << 16) | (uint32_t)__half_as_ushort(a);
}

// ---------------- merged weight transpose+convert (also zeroes g_cnt) ----------
#define T_W1   22528
#define T_W3   45056
#define T_W2   67584
#define T_S1   69120
#define T_S3   70656
#define T_ALL  72192

__device__ __forceinline__ void cvt_tile(const float* __restrict__ in,
                                         fp16* __restrict__ out,
                                         int K, int N, int kt, int nt) {
    __shared__ float tile[32][33];
    int k0 = kt * 32, n0 = nt * 32;
    int idx = threadIdx.x;
    int tx = idx & 31, ty = idx >> 5;
#pragma unroll
    for (int j = 0; j < 4; j++)
        tile[ty + 8 * j][tx] = in[(size_t)(k0 + ty + 8 * j) * N + (n0 + tx)];
    __syncthreads();
    int nl = idx >> 3, kq = (idx & 7) * 4;
    float v0 = tile[kq + 0][nl], v1 = tile[kq + 1][nl];
    float v2 = tile[kq + 2][nl], v3 = tile[kq + 3][nl];
    uint2 o;
    o.x = pack2(__float2half(v0), __float2half(v1));
    o.y = pack2(__float2half(v2), __float2half(v3));
    *reinterpret_cast<uint2*>(out + (size_t)(n0 + nl) * K + k0 + kq) = o;
}

__global__ void __launch_bounds__(256)
cvt_all_kernel(const float* __restrict__ w1, const float* __restrict__ w3,
               const float* __restrict__ w2, const float* __restrict__ sw1,
               const float* __restrict__ sw3, const float* __restrict__ sw2) {
    int t = blockIdx.x;
    if (t == 0 && threadIdx.x < NEXP) g_cnt[threadIdx.x] = 0;
    if (t < T_W1) {
        int z = t / (32 * 88), r = t % (32 * 88);
        cvt_tile(w1 + (size_t)z * DIM * EHID, g_w1h + (size_t)z * EHID * DIM,
                 DIM, EHID, r % 32, r / 32);
    } else if (t < T_W3) {
        t -= T_W1;
        int z = t / (32 * 88), r = t % (32 * 88);
        cvt_tile(w3 + (size_t)z * DIM * EHID, g_w3h + (size_t)z * EHID * DIM,
                 DIM, EHID, r % 32, r / 32);
    } else if (t < T_W2) {
        t -= T_W3;
        int z = t / (88 * 32), r = t % (88 * 32);
        cvt_tile(w2 + (size_t)z * EHID * DIM, g_w2h + (size_t)z * DIM * EHID,
                 EHID, DIM, r % 88, r / 88);
    } else if (t < T_S1) {
        t -= T_W2;
        cvt_tile(sw1, g_s1h, DIM, SHID, t % 32, t / 32);
    } else if (t < T_S3) {
        t -= T_S1;
        cvt_tile(sw3, g_s3h, DIM, SHID, t % 32, t / 32);
    } else {
        t -= T_S3;
        cvt_tile(sw2, g_s2h, SHID, DIM, t % 48, t / 48);
    }
}

// ---------------- fused gate + x->fp16 conversion ------------------------------
__global__ void gate_kernel(const float* __restrict__ x, const float* __restrict__ gw) {
    int tok  = (blockIdx.x * blockDim.x + threadIdx.x) >> 5;
    int lane = threadIdx.x & 31;
    if (tok >= TOK) return;
    const float4* xr = reinterpret_cast<const float4*>(x + (size_t)tok * DIM);
    uint2* xo = reinterpret_cast<uint2*>(g_xh + (size_t)tok * DIM);
    float acc[NEXP];
#pragma unroll
    for (int e = 0; e < NEXP; e++) acc[e] = 0.f;
#pragma unroll
    for (int j = 0; j < 8; j++) {
        int q = lane + j * 32;
        float4 v = xr[q];
        uint2 ph;
        ph.x = pack2(__float2half(v.x), __float2half(v.y));
        ph.y = pack2(__float2half(v.z), __float2half(v.w));
        xo[q] = ph;
        int d = q * 4;
#pragma unroll
        for (int e = 0; e < NEXP; e++) {
            const float* gr = gw + e * DIM + d;
            acc[e] = fmaf(v.x, gr[0], acc[e]);
            acc[e] = fmaf(v.y, gr[1], acc[e]);
            acc[e] = fmaf(v.z, gr[2], acc[e]);
            acc[e] = fmaf(v.w, gr[3], acc[e]);
        }
    }
#pragma unroll
    for (int e = 0; e < NEXP; e++)
#pragma unroll
        for (int off = 16; off > 0; off >>= 1)
            acc[e] += __shfl_xor_sync(0xffffffffu, acc[e], off);
    if (lane == 0) {
        float mx = acc[0];
#pragma unroll
        for (int e = 1; e < NEXP; e++) mx = fmaxf(mx, acc[e]);
        float p[NEXP], s = 0.f;
#pragma unroll
        for (int e = 0; e < NEXP; e++) { p[e] = expf(acc[e] - mx); s += p[e]; }
        float inv = 1.f / s;
#pragma unroll
        for (int e = 0; e < NEXP; e++) p[e] *= inv;
        int i1 = 0;
#pragma unroll
        for (int e = 1; e < NEXP; e++) if (p[e] > p[i1]) i1 = e;
        int i2 = (i1 == 0) ? 1 : 0;
#pragma unroll
        for (int e = 0; e < NEXP; e++) if (e != i1 && p[e] > p[i2]) i2 = e;
        int pos1 = atomicAdd(&g_cnt[i1], 1);
        g_idx[i1 * TOK + pos1] = tok;  g_wgt[i1 * TOK + pos1] = p[i1];
        g_slot[2 * tok] = i1 * TOK + pos1;
        int pos2 = atomicAdd(&g_cnt[i2], 1);
        g_idx[i2 * TOK + pos2] = tok;  g_wgt[i2 * TOK + pos2] = p[i2];
        g_slot[2 * tok + 1] = i2 * TOK + pos2;
    }
}

// ---------------- GEMM1: fused SwiGLU up-proj (BK=64, 3-stage) ------------------
// grid.z in [0,8]: z<8 routed expert z, z==8 shared. BM=128, BN=64/matrix, BK=64.
// Stage (halves): A[128*72]=9216, B1[64*72]=4608 @9216, B3 @13824. STG=18432.
#define G1_S_AH   0
#define G1_S_B1H  9216
#define G1_S_B3H  13824
#define G1_STG    18432
#define G1_SMEM   (3 * G1_STG * 2)   // 110592 B

__global__ void __launch_bounds__(256, 2)
gemm1_kernel() {
    const int K = DIM;
    int z = blockIdx.z;
    bool sh = (z == NEXP);
    int M = sh ? TOK : g_cnt[z];
    int N = sh ? SHID : EHID;
    int rowBlock = blockIdx.y * 128;
    if (rowBlock >= M) return;
    int colBlock = blockIdx.x * 64;
    if (colBlock >= N) return;
    const fp16* B1 = sh ? g_s1h : g_w1h + (size_t)z * EHID * DIM;
    const fp16* B3 = sh ? g_s3h : g_w3h + (size_t)z * EHID * DIM;
    fp16* H        = sh ? g_hsh : g_hh  + (size_t)z * TOK * EHID;

    extern __shared__ __align__(16) fp16 sm1[];
    uint32_t sb0 = smem_u32(sm1);

    int tid = threadIdx.x, lane = tid & 31, warp = tid >> 5;
    int wm = warp >> 2, wn = warp & 3;

    // ---- global load mapping: one 128B row (8 cp16) per thread ----
    const fp16* src;
    uint32_t dstb;
    bool valid = true;
    {
        int row = tid;
        if (row < 128) {
            bool av = (rowBlock + row) < M;
            int asrc = av ? (sh ? rowBlock + row : g_idx[z * TOK + rowBlock + row]) : 0;
            src = g_xh + (size_t)asrc * K;
            valid = av;
            dstb = (uint32_t)(G1_S_AH + row * LDH) * 2;
        } else if (row < 192) {
            src = B1 + (size_t)(colBlock + row - 128) * K;
            dstb = (uint32_t)(G1_S_B1H + (row - 128) * LDH) * 2;
        } else {
            src = B3 + (size_t)(colBlock + row - 192) * K;
            dstb = (uint32_t)(G1_S_B3H + (row - 192) * LDH) * 2;
        }
    }
    auto load_stage = [&](int s, int k0) {
        uint32_t sb = sb0 + (uint32_t)s * G1_STG * 2;
#pragma unroll
        for (int c = 0; c < 8; c++)
            cp16(sb + dstb + c * 16, src + k0 + c * 8, valid);
    };

    // ---- ldmatrix bases ----
    int lrow = lane & 15, lkA = (lane >> 4) * 8;
    uint32_t aOff[4];
#pragma unroll
    for (int mi = 0; mi < 4; mi++) {
        int r = wm * 64 + mi * 16 + lrow;
        aOff[mi] = (uint32_t)(G1_S_AH + r * LDH + lkA) * 2;
    }
    int nloc = (lane & 7) | ((lane & 16) >> 1);
    int lkB  = ((lane >> 3) & 1) * 8;
    uint32_t bRow = (uint32_t)((wn * 16 + nloc) * LDH + lkB) * 2;
    uint32_t b1Off = G1_S_B1H * 2 + bRow;
    uint32_t b3Off = G1_S_B3H * 2 + bRow;

    float acc1[4][2][4], acc3[4][2][4];
#pragma unroll
    for (int i = 0; i < 4; i++)
#pragma unroll
        for (int j = 0; j < 2; j++)
#pragma unroll
            for (int r = 0; r < 4; r++) { acc1[i][j][r] = 0.f; acc3[i][j][r] = 0.f; }

    const int nIter = K / 64;           // 16
    load_stage(0, 0);
    CP_COMMIT();
    load_stage(1, 64);
    CP_COMMIT();
    int cur = 0, pre = 2;
    for (int i = 0; i < nIter; i++) {
        if (i < nIter - 1) { CP_WAIT1(); } else { CP_WAIT0(); }
        __syncthreads();
        if (i + 2 < nIter) { load_stage(pre, (i + 2) * 64); CP_COMMIT(); }
        uint32_t sb = sb0 + (uint32_t)cur * G1_STG * 2;
#pragma unroll
        for (int ks = 0; ks < 4; ks++) {
            uint32_t ko = (uint32_t)ks * 32;
            uint32_t ah[4][4];
#pragma unroll
            for (int mi = 0; mi < 4; mi++)
                LDSM4(ah[mi], sb + aOff[mi] + ko);
            uint32_t b1[4], b3[4];
            LDSM4(b1, sb + b1Off + ko);
            LDSM4(b3, sb + b3Off + ko);
#pragma unroll
            for (int mi = 0; mi < 4; mi++)
#pragma unroll
                for (int nf = 0; nf < 2; nf++) {
                    mma_f16(acc1[mi][nf], ah[mi], b1[2*nf], b1[2*nf+1]);
                    mma_f16(acc3[mi][nf], ah[mi], b3[2*nf], b3[2*nf+1]);
                }
        }
        cur = (cur == 2) ? 0 : cur + 1;
        pre = (pre == 2) ? 0 : pre + 1;
    }

    int rr = lane >> 2, cc = (lane & 3) * 2;
#pragma unroll
    for (int mi = 0; mi < 4; mi++) {
        int gmb = rowBlock + wm * 64 + mi * 16 + rr;
#pragma unroll
        for (int nf = 0; nf < 2; nf++) {
            int col = colBlock + wn * 16 + nf * 8 + cc;
#pragma unroll
            for (int hf = 0; hf < 2; hf++) {
                int gm = gmb + hf * 8;
                if (gm < M) {
                    float v1a = acc1[mi][nf][hf*2], v1b = acc1[mi][nf][hf*2+1];
                    float v3a = acc3[mi][nf][hf*2], v3b = acc3[mi][nf][hf*2+1];
                    float h0 = v1a / (1.f + expf(-v1a)) * v3a;
                    float h1 = v1b / (1.f + expf(-v1b)) * v3b;
                    *reinterpret_cast<uint32_t*>(H + (size_t)gm * N + col) =
                        pack2(__float2half(h0), __float2half(h1));
                }
            }
        }
    }
}

// ---------------- GEMM2: down-projection (BN=128, BK=64, 3-stage) ---------------
// Stage (halves): A[128*72]=9216, B[128*72] @9216. STG=18432.
#define G2_S_A   0
#define G2_S_B   9216
#define G2_STG   18432
#define G2_SMEM  (3 * G2_STG * 2)    // 110592 B

__global__ void __launch_bounds__(256, 2)
gemm2_kernel(float* __restrict__ out) {
    int z = blockIdx.z;
    bool sh = (z == NEXP);
    int M = sh ? TOK : g_cnt[z];
    int K = sh ? SHID : EHID;
    int rowBlock = blockIdx.y * 128;
    if (rowBlock >= M) return;
    int colBlock = blockIdx.x * 128;
    const fp16* A = sh ? g_hsh : g_hh + (size_t)z * TOK * EHID;
    const fp16* B = sh ? g_s2h : g_w2h + (size_t)z * DIM * EHID;
    float* Y      = sh ? out   : g_yp  + (size_t)z * TOK * DIM;

    extern __shared__ __align__(16) fp16 sm2[];
    uint32_t sb0 = smem_u32(sm2);

    int tid = threadIdx.x, lane = tid & 31, warp = tid >> 5;
    int wm = warp >> 2, wn = warp & 3;

    // one 128B row per thread
    const fp16* src;
    uint32_t dstb;
    bool valid = true;
    {
        int row = tid;
        if (row < 128) {
            bool av = (rowBlock + row) < M;
            src = A + (size_t)(av ? rowBlock + row : 0) * K;
            valid = av;
            dstb = (uint32_t)(G2_S_A + row * LDH) * 2;
        } else {
            src = B + (size_t)(colBlock + row - 128) * K;
            dstb = (uint32_t)(G2_S_B + (row - 128) * LDH) * 2;
        }
    }
    auto load_stage = [&](int s, int k0) {
        uint32_t sb = sb0 + (uint32_t)s * G2_STG * 2;
#pragma unroll
        for (int c = 0; c < 8; c++)
            cp16(sb + dstb + c * 16, src + k0 + c * 8, valid);
    };

    int lrow = lane & 15, lkA = (lane >> 4) * 8;
    uint32_t aOff[4];
#pragma unroll
    for (int mi = 0; mi < 4; mi++) {
        int r = wm * 64 + mi * 16 + lrow;
        aOff[mi] = (uint32_t)(G2_S_A + r * LDH + lkA) * 2;
    }
    int nloc = (lane & 7) | ((lane & 16) >> 1);
    int lkB  = ((lane >> 3) & 1) * 8;
    uint32_t bOff[2];
#pragma unroll
    for (int ng = 0; ng < 2; ng++) {
        int n = wn * 32 + ng * 16 + nloc;
        bOff[ng] = (uint32_t)(G2_S_B + n * LDH + lkB) * 2;
    }

    float acc[4][4][4];
#pragma unroll
    for (int i = 0; i < 4; i++)
#pragma unroll
        for (int j = 0; j < 4; j++)
#pragma unroll
            for (int r = 0; r < 4; r++) acc[i][j][r] = 0.f;

    const int nIter = K / 64;           // 44 or 24
    load_stage(0, 0);
    CP_COMMIT();
    load_stage(1, 64);
    CP_COMMIT();
    int cur = 0, pre = 2;
    for (int i = 0; i < nIter; i++) {
        if (i < nIter - 1) { CP_WAIT1(); } else { CP_WAIT0(); }
        __syncthreads();
        if (i + 2 < nIter) { load_stage(pre, (i + 2) * 64); CP_COMMIT(); }
        uint32_t sb = sb0 + (uint32_t)cur * G2_STG * 2;
#pragma unroll
        for (int ks = 0; ks < 4; ks++) {
            uint32_t ko = (uint32_t)ks * 32;
            uint32_t ah[4][4];
#pragma unroll
            for (int mi = 0; mi < 4; mi++)
                LDSM4(ah[mi], sb + aOff[mi] + ko);
            uint32_t b[2][4];
#pragma unroll
            for (int ng = 0; ng < 2; ng++)
                LDSM4(b[ng], sb + bOff[ng] + ko);
#pragma unroll
            for (int mi = 0; mi < 4; mi++)
#pragma unroll
                for (int nf = 0; nf < 4; nf++)
                    mma_f16(acc[mi][nf], ah[mi], b[nf >> 1][(nf & 1) * 2],
                            b[nf >> 1][(nf & 1) * 2 + 1]);
        }
        cur = (cur == 2) ? 0 : cur + 1;
        pre = (pre == 2) ? 0 : pre + 1;
    }

    int rr = lane >> 2, cc = (lane & 3) * 2;
#pragma unroll
    for (int mi = 0; mi < 4; mi++) {
        int gmb = rowBlock + wm * 64 + mi * 16 + rr;
#pragma unroll
        for (int hf = 0; hf < 2; hf++) {
            int gm = gmb + hf * 8;
            if (gm < M) {
                float w = sh ? 1.0f : g_wgt[z * TOK + gm];
                float* dst = Y + (size_t)gm * DIM;
#pragma unroll
                for (int nf = 0; nf < 4; nf++) {
                    int col = colBlock + wn * 32 + nf * 8 + cc;
                    float2 v;
                    v.x = w * acc[mi][nf][hf*2];
                    v.y = w * acc[mi][nf][hf*2+1];
                    *reinterpret_cast<float2*>(dst + col) = v;
                }
            }
        }
    }
}

// out[t] += yp[slot0(t)] + yp[slot1(t)]
__global__ void combine_kernel(float* __restrict__ out) {
    int t = blockIdx.x;
    int d = threadIdx.x;
    int s0 = g_slot[2 * t], s1 = g_slot[2 * t + 1];
    float4* o = reinterpret_cast<float4*>(out) + (size_t)t * 256 + d;
    const float4 a  = *o;
    const float4 b0 = reinterpret_cast<const float4*>(g_yp)[(size_t)s0 * 256 + d];
    const float4 b1 = reinterpret_cast<const float4*>(g_yp)[(size_t)s1 * 256 + d];
    float4 r;
    r.x = a.x + (b0.x + b1.x);
    r.y = a.y + (b0.y + b1.y);
    r.z = a.z + (b0.z + b1.z);
    r.w = a.w + (b0.w + b1.w);
    *o = r;
}

// ---------------- launcher -----------------------------------------------------
extern "C" void kernel_launch(void* const* d_in, const int* in_sizes, int n_in,
                              void* d_out, int out_size) {
    const float* x   = (const float*)d_in[0];
    const float* gw  = (const float*)d_in[1];
    const float* w1  = (const float*)d_in[2];
    const float* w2  = (const float*)d_in[3];
    const float* w3  = (const float*)d_in[4];
    const float* sw1 = (const float*)d_in[5];
    const float* sw2 = (const float*)d_in[6];
    const float* sw3 = (const float*)d_in[7];
    float* out = (float*)d_out;
    (void)in_sizes; (void)n_in; (void)out_size;

    cudaFuncSetAttribute(gemm1_kernel, cudaFuncAttributeMaxDynamicSharedMemorySize, G1_SMEM);
    cudaFuncSetAttribute(gemm2_kernel, cudaFuncAttributeMaxDynamicSharedMemorySize, G2_SMEM);

    // conversions (also zeroes g_cnt in block 0)
    cvt_all_kernel<<<T_ALL, 256>>>(w1, w3, w2, sw1, sw3, sw2);
    // fused gate + x->fp16
    gate_kernel<<<TOK / 8, 256>>>(x, gw);

    // merged up-proj: z<8 routed experts, z==8 shared expert
    gemm1_kernel<<<dim3(EHID / 64, TOK / 128, NEXP + 1), 256, G1_SMEM>>>();
    // merged down-proj: shared writes d_out, routed writes yp partials
    gemm2_kernel<<<dim3(DIM / 128, TOK / 128, NEXP + 1), 256, G2_SMEM>>>(out);

    combine_kernel<<<TOK, 256>>>(out);
}

// round 13
// speedup vs baseline: 1.3265x; 1.3265x over previous
#include <cuda_runtime.h>
#include <cuda_fp16.h>
#include <math.h>
#include <stdint.h>

#define TOK   4096
#define DIM   1024
#define NEXP  8
#define EHID  2816
#define SHID  1536
#define LDH   40      // smem row stride in fp16 elems (32 data + 8 pad)

typedef __half fp16;

// ---------------- scratch (device globals) ----------------------------------
__device__ fp16  g_xh [(size_t)TOK*DIM];
__device__ fp16  g_w1h[(size_t)NEXP*EHID*DIM];
__device__ fp16  g_w3h[(size_t)NEXP*EHID*DIM];
__device__ fp16  g_w2h[(size_t)NEXP*DIM*EHID];
__device__ fp16  g_s1h[(size_t)SHID*DIM];
__device__ fp16  g_s3h[(size_t)SHID*DIM];
__device__ fp16  g_s2h[(size_t)DIM*SHID];
__device__ fp16  g_hh [(size_t)NEXP*TOK*EHID];   // routed hidden (fp16)
__device__ fp16  g_hsh[(size_t)TOK*SHID];        // shared hidden
__device__ float g_yp [(size_t)NEXP*TOK*DIM];
__device__ int   g_cnt[NEXP];
__device__ int   g_idx[NEXP*TOK];
__device__ float g_wgt[NEXP*TOK];
__device__ int   g_slot[TOK*2];

// ---------------- helpers ----------------------------------------------------
__device__ __forceinline__ uint32_t smem_u32(const void* p) {
    uint32_t a;
    asm("{ .reg .u64 t; cvta.to.shared.u64 t, %1; cvt.u32.u64 %0, t; }"
        : "=r"(a) : "l"(p));
    return a;
}
__device__ __forceinline__ void cp16(uint32_t saddr, const void* g, bool valid) {
    int sz = valid ? 16 : 0;
    asm volatile("cp.async.cg.shared.global [%0], [%1], 16, %2;"
                 :: "r"(saddr), "l"(g), "r"(sz));
}
#define CP_COMMIT() asm volatile("cp.async.commit_group;")
#define CP_WAIT2()  asm volatile("cp.async.wait_group 2;")
#define CP_WAIT1()  asm volatile("cp.async.wait_group 1;")
#define CP_WAIT0()  asm volatile("cp.async.wait_group 0;")

#define LDSM4(r, addr) \
    asm volatile("ldmatrix.sync.aligned.m8n8.x4.shared.b16 {%0,%1,%2,%3}, [%4];" \
        : "=r"((r)[0]), "=r"((r)[1]), "=r"((r)[2]), "=r"((r)[3]) : "r"(addr))

__device__ __forceinline__ void mma_f16(float d[4], const uint32_t a[4],
                                        uint32_t b0, uint32_t b1) {
    asm volatile(
        "mma.sync.aligned.m16n8k16.row.col.f32.f16.f16.f32 "
        "{%0,%1,%2,%3},{%4,%5,%6,%7},{%8,%9},{%0,%1,%2,%3};"
        : "+f"(d[0]), "+f"(d[1]), "+f"(d[2]), "+f"(d[3])
        : "r"(a[0]), "r"(a[1]), "r"(a[2]), "r"(a[3]), "r"(b0), "r"(b1));
}

__device__ __forceinline__ uint32_t pack2(fp16 a, fp16 b) {
    return ((uint32_t)__half_as_ushort(b) << 16) | (uint32_t)__half_as_ushort(a);
}

// ---------------- merged weight transpose+convert (also zeroes g_cnt) ----------
#define T_W1   22528
#define T_W3   45056
#define T_W2   67584
#define T_S1   69120
#define T_S3   70656
#define T_ALL  72192

__device__ __forceinline__ void cvt_tile(const float* __restrict__ in,
                                         fp16* __restrict__ out,
                                         int K, int N, int kt, int nt) {
    __shared__ float tile[32][33];
    int k0 = kt * 32, n0 = nt * 32;
    int idx = threadIdx.x;
    int tx = idx & 31, ty = idx >> 5;
#pragma unroll
    for (int j = 0; j < 4; j++)
        tile[ty + 8 * j][tx] = in[(size_t)(k0 + ty + 8 * j) * N + (n0 + tx)];
    __syncthreads();
    int nl = idx >> 3, kq = (idx & 7) * 4;
    float v0 = tile[kq + 0][nl], v1 = tile[kq + 1][nl];
    float v2 = tile[kq + 2][nl], v3 = tile[kq + 3][nl];
    uint2 o;
    o.x = pack2(__float2half(v0), __float2half(v1));
    o.y = pack2(__float2half(v2), __float2half(v3));
    *reinterpret_cast<uint2*>(out + (size_t)(n0 + nl) * K + k0 + kq) = o;
}

__global__ void __launch_bounds__(256)
cvt_all_kernel(const float* __restrict__ w1, const float* __restrict__ w3,
               const float* __restrict__ w2, const float* __restrict__ sw1,
               const float* __restrict__ sw3, const float* __restrict__ sw2) {
    int t = blockIdx.x;
    if (t == 0 && threadIdx.x < NEXP) g_cnt[threadIdx.x] = 0;
    if (t < T_W1) {
        int z = t / (32 * 88), r = t % (32 * 88);
        cvt_tile(w1 + (size_t)z * DIM * EHID, g_w1h + (size_t)z * EHID * DIM,
                 DIM, EHID, r % 32, r / 32);
    } else if (t < T_W3) {
        t -= T_W1;
        int z = t / (32 * 88), r = t % (32 * 88);
        cvt_tile(w3 + (size_t)z * DIM * EHID, g_w3h + (size_t)z * EHID * DIM,
                 DIM, EHID, r % 32, r / 32);
    } else if (t < T_W2) {
        t -= T_W3;
        int z = t / (88 * 32), r = t % (88 * 32);
        cvt_tile(w2 + (size_t)z * EHID * DIM, g_w2h + (size_t)z * DIM * EHID,
                 EHID, DIM, r % 88, r / 88);
    } else if (t < T_S1) {
        t -= T_W2;
        cvt_tile(sw1, g_s1h, DIM, SHID, t % 32, t / 32);
    } else if (t < T_S3) {
        t -= T_S1;
        cvt_tile(sw3, g_s3h, DIM, SHID, t % 32, t / 32);
    } else {
        t -= T_S3;
        cvt_tile(sw2, g_s2h, SHID, DIM, t % 48, t / 48);
    }
}

// ---------------- fused gate + x->fp16 conversion ------------------------------
__global__ void gate_kernel(const float* __restrict__ x, const float* __restrict__ gw) {
    int tok  = (blockIdx.x * blockDim.x + threadIdx.x) >> 5;
    int lane = threadIdx.x & 31;
    if (tok >= TOK) return;
    const float4* xr = reinterpret_cast<const float4*>(x + (size_t)tok * DIM);
    uint2* xo = reinterpret_cast<uint2*>(g_xh + (size_t)tok * DIM);
    float acc[NEXP];
#pragma unroll
    for (int e = 0; e < NEXP; e++) acc[e] = 0.f;
#pragma unroll
    for (int j = 0; j < 8; j++) {
        int q = lane + j * 32;
        float4 v = xr[q];
        uint2 ph;
        ph.x = pack2(__float2half(v.x), __float2half(v.y));
        ph.y = pack2(__float2half(v.z), __float2half(v.w));
        xo[q] = ph;
        int d = q * 4;
#pragma unroll
        for (int e = 0; e < NEXP; e++) {
            const float* gr = gw + e * DIM + d;
            acc[e] = fmaf(v.x, gr[0], acc[e]);
            acc[e] = fmaf(v.y, gr[1], acc[e]);
            acc[e] = fmaf(v.z, gr[2], acc[e]);
            acc[e] = fmaf(v.w, gr[3], acc[e]);
        }
    }
#pragma unroll
    for (int e = 0; e < NEXP; e++)
#pragma unroll
        for (int off = 16; off > 0; off >>= 1)
            acc[e] += __shfl_xor_sync(0xffffffffu, acc[e], off);
    if (lane == 0) {
        float mx = acc[0];
#pragma unroll
        for (int e = 1; e < NEXP; e++) mx = fmaxf(mx, acc[e]);
        float p[NEXP], s = 0.f;
#pragma unroll
        for (int e = 0; e < NEXP; e++) { p[e] = expf(acc[e] - mx); s += p[e]; }
        float inv = 1.f / s;
#pragma unroll
        for (int e = 0; e < NEXP; e++) p[e] *= inv;
        int i1 = 0;
#pragma unroll
        for (int e = 1; e < NEXP; e++) if (p[e] > p[i1]) i1 = e;
        int i2 = (i1 == 0) ? 1 : 0;
#pragma unroll
        for (int e = 0; e < NEXP; e++) if (e != i1 && p[e] > p[i2]) i2 = e;
        int pos1 = atomicAdd(&g_cnt[i1], 1);
        g_idx[i1 * TOK + pos1] = tok;  g_wgt[i1 * TOK + pos1] = p[i1];
        g_slot[2 * tok] = i1 * TOK + pos1;
        int pos2 = atomicAdd(&g_cnt[i2], 1);
        g_idx[i2 * TOK + pos2] = tok;  g_wgt[i2 * TOK + pos2] = p[i2];
        g_slot[2 * tok + 1] = i2 * TOK + pos2;
    }
}

// ---------------- GEMM1: fused SwiGLU up-proj (BK=32, 4-stage) ------------------
// grid.z in [0,8]: z<8 routed expert z, z==8 shared. BM=128, BN=64/matrix.
#define G1_S_AH   0
#define G1_S_B1H  5120
#define G1_S_B3H  7680
#define G1_STG    10240
#define G1_SMEM   (4 * G1_STG * 2)   // 81920 B

__global__ void __launch_bounds__(256, 2)
gemm1_kernel() {
    const int K = DIM;
    int z = blockIdx.z;
    bool sh = (z == NEXP);
    int M = sh ? TOK : g_cnt[z];
    int N = sh ? SHID : EHID;
    int rowBlock = blockIdx.y * 128;
    if (rowBlock >= M) return;
    int colBlock = blockIdx.x * 64;
    if (colBlock >= N) return;
    const fp16* B1 = sh ? g_s1h : g_w1h + (size_t)z * EHID * DIM;
    const fp16* B3 = sh ? g_s3h : g_w3h + (size_t)z * EHID * DIM;
    fp16* H        = sh ? g_hsh : g_hh  + (size_t)z * TOK * EHID;

    extern __shared__ __align__(16) fp16 sm1[];
    uint32_t sb0 = smem_u32(sm1);

    int tid = threadIdx.x, lane = tid & 31, warp = tid >> 5;
    int wm = warp >> 2, wn = warp & 3;

    int ra = tid >> 1, ka = (tid & 1) * 16;
    bool aval = (rowBlock + ra) < M;
    int asrc = aval ? (sh ? rowBlock + ra : g_idx[z * TOK + rowBlock + ra]) : 0;
    const fp16* aph = g_xh + (size_t)asrc * K + ka;
    uint32_t adst = (uint32_t)(ra * LDH + ka) * 2;

    int rb = tid >> 2, kb = (tid & 3) * 8;
    const fp16* b1p = B1 + (size_t)(colBlock + rb) * K + kb;
    const fp16* b3p = B3 + (size_t)(colBlock + rb) * K + kb;
    uint32_t bdst = (uint32_t)(rb * LDH + kb) * 2;

    auto load_stage = [&](int s, int k0) {
        uint32_t sb = sb0 + (uint32_t)s * G1_STG * 2;
        cp16(sb + G1_S_AH * 2 + adst,      aph + k0,     aval);
        cp16(sb + G1_S_AH * 2 + adst + 16, aph + k0 + 8, aval);
        cp16(sb + G1_S_B1H * 2 + bdst, b1p + k0, true);
        cp16(sb + G1_S_B3H * 2 + bdst, b3p + k0, true);
    };

    int lrow = lane & 15, lkA = (lane >> 4) * 8;
    uint32_t aOff[4];
#pragma unroll
    for (int mi = 0; mi < 4; mi++) {
        int r = wm * 64 + mi * 16 + lrow;
        aOff[mi] = (uint32_t)(G1_S_AH + r * LDH + lkA) * 2;
    }
    int nloc = (lane & 7) | ((lane & 16) >> 1);
    int lkB  = ((lane >> 3) & 1) * 8;
    uint32_t bRow = (uint32_t)((wn * 16 + nloc) * LDH + lkB) * 2;
    uint32_t b1Off = G1_S_B1H * 2 + bRow;
    uint32_t b3Off = G1_S_B3H * 2 + bRow;

    float acc1[4][2][4], acc3[4][2][4];
#pragma unroll
    for (int i = 0; i < 4; i++)
#pragma unroll
        for (int j = 0; j < 2; j++)
#pragma unroll
            for (int r = 0; r < 4; r++) { acc1[i][j][r] = 0.f; acc3[i][j][r] = 0.f; }

    const int nIter = K / 32;           // 32
    load_stage(0, 0);  CP_COMMIT();
    load_stage(1, 32); CP_COMMIT();
    load_stage(2, 64); CP_COMMIT();
    int cur = 0, pre = 3;
    for (int i = 0; i < nIter; i++) {
        int left = nIter - 1 - i;
        if (left >= 2)      { CP_WAIT2(); }
        else if (left == 1) { CP_WAIT1(); }
        else                { CP_WAIT0(); }
        __syncthreads();
        if (i + 3 < nIter) { load_stage(pre, (i + 3) * 32); CP_COMMIT(); }
        uint32_t sb = sb0 + (uint32_t)cur * G1_STG * 2;
#pragma unroll
        for (int ks = 0; ks < 2; ks++) {
            uint32_t ko = (uint32_t)ks * 32;
            uint32_t ah[4][4];
#pragma unroll
            for (int mi = 0; mi < 4; mi++)
                LDSM4(ah[mi], sb + aOff[mi] + ko);
            uint32_t b1[4], b3[4];
            LDSM4(b1, sb + b1Off + ko);
            LDSM4(b3, sb + b3Off + ko);
#pragma unroll
            for (int mi = 0; mi < 4; mi++)
#pragma unroll
                for (int nf = 0; nf < 2; nf++) {
                    mma_f16(acc1[mi][nf], ah[mi], b1[2*nf], b1[2*nf+1]);
                    mma_f16(acc3[mi][nf], ah[mi], b3[2*nf], b3[2*nf+1]);
                }
        }
        cur = (cur + 1) & 3;
        pre = (pre + 1) & 3;
    }

    int rr = lane >> 2, cc = (lane & 3) * 2;
#pragma unroll
    for (int mi = 0; mi < 4; mi++) {
        int gmb = rowBlock + wm * 64 + mi * 16 + rr;
#pragma unroll
        for (int nf = 0; nf < 2; nf++) {
            int col = colBlock + wn * 16 + nf * 8 + cc;
#pragma unroll
            for (int hf = 0; hf < 2; hf++) {
                int gm = gmb + hf * 8;
                if (gm < M) {
                    float v1a = acc1[mi][nf][hf*2], v1b = acc1[mi][nf][hf*2+1];
                    float v3a = acc3[mi][nf][hf*2], v3b = acc3[mi][nf][hf*2+1];
                    float h0 = v1a / (1.f + expf(-v1a)) * v3a;
                    float h1 = v1b / (1.f + expf(-v1b)) * v3b;
                    *reinterpret_cast<uint32_t*>(H + (size_t)gm * N + col) =
                        pack2(__float2half(h0), __float2half(h1));
                }
            }
        }
    }
}

// ---------------- GEMM2: down-projection (BN=128, BK=32, 4-stage) ---------------
#define G2_S_A   0
#define G2_S_B   5120
#define G2_STG   10240
#define G2_SMEM  (4 * G2_STG * 2)    // 81920 B

__global__ void __launch_bounds__(256, 2)
gemm2_kernel(float* __restrict__ out) {
    int z = blockIdx.z;
    bool sh = (z == NEXP);
    int M = sh ? TOK : g_cnt[z];
    int K = sh ? SHID : EHID;
    int rowBlock = blockIdx.y * 128;
    if (rowBlock >= M) return;
    int colBlock = blockIdx.x * 128;
    const fp16* A = sh ? g_hsh : g_hh + (size_t)z * TOK * EHID;
    const fp16* B = sh ? g_s2h : g_w2h + (size_t)z * DIM * EHID;
    float* Y      = sh ? out   : g_yp  + (size_t)z * TOK * DIM;

    extern __shared__ __align__(16) fp16 sm2[];
    uint32_t sb0 = smem_u32(sm2);

    int tid = threadIdx.x, lane = tid & 31, warp = tid >> 5;
    int wm = warp >> 2, wn = warp & 3;

    int ra = tid >> 1, ka = (tid & 1) * 16;
    bool aval = (rowBlock + ra) < M;
    const fp16* aph = A + (size_t)(aval ? rowBlock + ra : 0) * K + ka;
    const fp16* bph = B + (size_t)(colBlock + ra) * K + ka;
    uint32_t adst = (uint32_t)(ra * LDH + ka) * 2;

    auto load_stage = [&](int s, int k0) {
        uint32_t sb = sb0 + (uint32_t)s * G2_STG * 2;
        cp16(sb + G2_S_A * 2 + adst,      aph + k0,     aval);
        cp16(sb + G2_S_A * 2 + adst + 16, aph + k0 + 8, aval);
        cp16(sb + G2_S_B * 2 + adst,      bph + k0,     true);
        cp16(sb + G2_S_B * 2 + adst + 16, bph + k0 + 8, true);
    };

    int lrow = lane & 15, lkA = (lane >> 4) * 8;
    uint32_t aOff[4];
#pragma unroll
    for (int mi = 0; mi < 4; mi++) {
        int r = wm * 64 + mi * 16 + lrow;
        aOff[mi] = (uint32_t)(G2_S_A + r * LDH + lkA) * 2;
    }
    int nloc = (lane & 7) | ((lane & 16) >> 1);
    int lkB  = ((lane >> 3) & 1) * 8;
    uint32_t bOff[2];
#pragma unroll
    for (int ng = 0; ng < 2; ng++) {
        int n = wn * 32 + ng * 16 + nloc;
        bOff[ng] = (uint32_t)(G2_S_B + n * LDH + lkB) * 2;
    }

    float acc[4][4][4];
#pragma unroll
    for (int i = 0; i < 4; i++)
#pragma unroll
        for (int j = 0; j < 4; j++)
#pragma unroll
            for (int r = 0; r < 4; r++) acc[i][j][r] = 0.f;

    const int nIter = K / 32;           // 88 or 48
    load_stage(0, 0);  CP_COMMIT();
    load_stage(1, 32); CP_COMMIT();
    load_stage(2, 64); CP_COMMIT();
    int cur = 0, pre = 3;
    for (int i = 0; i < nIter; i++) {
        int left = nIter - 1 - i;
        if (left >= 2)      { CP_WAIT2(); }
        else if (left == 1) { CP_WAIT1(); }
        else                { CP_WAIT0(); }
        __syncthreads();
        if (i + 3 < nIter) { load_stage(pre, (i + 3) * 32); CP_COMMIT(); }
        uint32_t sb = sb0 + (uint32_t)cur * G2_STG * 2;
#pragma unroll
        for (int ks = 0; ks < 2; ks++) {
            uint32_t ko = (uint32_t)ks * 32;
            uint32_t ah[4][4];
#pragma unroll
            for (int mi = 0; mi < 4; mi++)
                LDSM4(ah[mi], sb + aOff[mi] + ko);
            uint32_t b[2][4];
#pragma unroll
            for (int ng = 0; ng < 2; ng++)
                LDSM4(b[ng], sb + bOff[ng] + ko);
#pragma unroll
            for (int mi = 0; mi < 4; mi++)
#pragma unroll
                for (int nf = 0; nf < 4; nf++)
                    mma_f16(acc[mi][nf], ah[mi], b[nf >> 1][(nf & 1) * 2],
                            b[nf >> 1][(nf & 1) * 2 + 1]);
        }
        cur = (cur + 1) & 3;
        pre = (pre + 1) & 3;
    }

    int rr = lane >> 2, cc = (lane & 3) * 2;
#pragma unroll
    for (int mi = 0; mi < 4; mi++) {
        int gmb = rowBlock + wm * 64 + mi * 16 + rr;
#pragma unroll
        for (int hf = 0; hf < 2; hf++) {
            int gm = gmb + hf * 8;
            if (gm < M) {
                float w = sh ? 1.0f : g_wgt[z * TOK + gm];
                float* dst = Y + (size_t)gm * DIM;
#pragma unroll
                for (int nf = 0; nf < 4; nf++) {
                    int col = colBlock + wn * 32 + nf * 8 + cc;
                    float2 v;
                    v.x = w * acc[mi][nf][hf*2];
                    v.y = w * acc[mi][nf][hf*2+1];
                    *reinterpret_cast<float2*>(dst + col) = v;
                }
            }
        }
    }
}

// out[t] += yp[slot0(t)] + yp[slot1(t)]
__global__ void combine_kernel(float* __restrict__ out) {
    int t = blockIdx.x;
    int d = threadIdx.x;
    int s0 = g_slot[2 * t], s1 = g_slot[2 * t + 1];
    float4* o = reinterpret_cast<float4*>(out) + (size_t)t * 256 + d;
    const float4 a  = *o;
    const float4 b0 = reinterpret_cast<const float4*>(g_yp)[(size_t)s0 * 256 + d];
    const float4 b1 = reinterpret_cast<const float4*>(g_yp)[(size_t)s1 * 256 + d];
    float4 r;
    r.x = a.x + (b0.x + b1.x);
    r.y = a.y + (b0.y + b1.y);
    r.z = a.z + (b0.z + b1.z);
    r.w = a.w + (b0.w + b1.w);
    *o = r;
}

// ---------------- launcher -----------------------------------------------------
extern "C" void kernel_launch(void* const* d_in, const int* in_sizes, int n_in,
                              void* d_out, int out_size) {
    const float* x   = (const float*)d_in[0];
    const float* gw  = (const float*)d_in[1];
    const float* w1  = (const float*)d_in[2];
    const float* w2  = (const float*)d_in[3];
    const float* w3  = (const float*)d_in[4];
    const float* sw1 = (const float*)d_in[5];
    const float* sw2 = (const float*)d_in[6];
    const float* sw3 = (const float*)d_in[7];
    float* out = (float*)d_out;
    (void)in_sizes; (void)n_in; (void)out_size;

    cudaFuncSetAttribute(gemm1_kernel, cudaFuncAttributeMaxDynamicSharedMemorySize, G1_SMEM);
    cudaFuncSetAttribute(gemm2_kernel, cudaFuncAttributeMaxDynamicSharedMemorySize, G2_SMEM);

    // conversions (also zeroes g_cnt in block 0)
    cvt_all_kernel<<<T_ALL, 256>>>(w1, w3, w2, sw1, sw3, sw2);
    // fused gate + x->fp16
    gate_kernel<<<TOK / 8, 256>>>(x, gw);

    // merged up-proj: z<8 routed experts, z==8 shared expert
    gemm1_kernel<<<dim3(EHID / 64, TOK / 128, NEXP + 1), 256, G1_SMEM>>>();
    // merged down-proj: shared writes d_out, routed writes yp partials
    gemm2_kernel<<<dim3(DIM / 128, TOK / 128, NEXP + 1), 256, G2_SMEM>>>(out);

    combine_kernel<<<TOK, 256>>>(out);
}

// round 14
// speedup vs baseline: 1.3342x; 1.0058x over previous
#include <cuda_runtime.h>
#include <cuda_fp16.h>
#include <math.h>
#include <stdint.h>

#define TOK   4096
#define DIM   1024
#define NEXP  8
#define EHID  2816
#define SHID  1536
#define LDH   40      // smem row stride in fp16 elems (32 data + 8 pad)

typedef __half fp16;

// ---------------- scratch (device globals; zero-initialized at load) ---------
__device__ fp16  g_xh [(size_t)TOK*DIM];
__device__ fp16  g_w1h[(size_t)NEXP*EHID*DIM];
__device__ fp16  g_w3h[(size_t)NEXP*EHID*DIM];
__device__ fp16  g_w2h[(size_t)NEXP*DIM*EHID];
__device__ fp16  g_s1h[(size_t)SHID*DIM];
__device__ fp16  g_s3h[(size_t)SHID*DIM];
__device__ fp16  g_s2h[(size_t)DIM*SHID];
__device__ fp16  g_hh [(size_t)NEXP*TOK*EHID];   // routed hidden (fp16)
__device__ fp16  g_hsh[(size_t)TOK*SHID];        // shared hidden
__device__ float g_yp [(size_t)NEXP*TOK*DIM];
__device__ int   g_cnt[NEXP];                    // zeroed by combine_kernel tail
__device__ int   g_idx[NEXP*TOK];
__device__ float g_wgt[NEXP*TOK];
__device__ int   g_slot[TOK*2];

// ---------------- helpers ----------------------------------------------------
__device__ __forceinline__ uint32_t smem_u32(const void* p) {
    uint32_t a;
    asm("{ .reg .u64 t; cvta.to.shared.u64 t, %1; cvt.u32.u64 %0, t; }"
        : "=r"(a) : "l"(p));
    return a;
}
__device__ __forceinline__ void cp16(uint32_t saddr, const void* g, bool valid) {
    int sz = valid ? 16 : 0;
    asm volatile("cp.async.cg.shared.global [%0], [%1], 16, %2;"
                 :: "r"(saddr), "l"(g), "r"(sz));
}
#define CP_COMMIT() asm volatile("cp.async.commit_group;")
#define CP_WAIT1()  asm volatile("cp.async.wait_group 1;")
#define CP_WAIT0()  asm volatile("cp.async.wait_group 0;")

#define LDSM4(r, addr) \
    asm volatile("ldmatrix.sync.aligned.m8n8.x4.shared.b16 {%0,%1,%2,%3}, [%4];" \
        : "=r"((r)[0]), "=r"((r)[1]), "=r"((r)[2]), "=r"((r)[3]) : "r"(addr))

__device__ __forceinline__ void mma_f16(float d[4], const uint32_t a[4],
                                        uint32_t b0, uint32_t b1) {
    asm volatile(
        "mma.sync.aligned.m16n8k16.row.col.f32.f16.f16.f32 "
        "{%0,%1,%2,%3},{%4,%5,%6,%7},{%8,%9},{%0,%1,%2,%3};"
        : "+f"(d[0]), "+f"(d[1]), "+f"(d[2]), "+f"(d[3])
        : "r"(a[0]), "r"(a[1]), "r"(a[2]), "r"(a[3]), "r"(b0), "r"(b1));
}

__device__ __forceinline__ uint32_t pack2(fp16 a, fp16 b) {
    return ((uint32_t)__half_as_ushort(b) << 16) | (uint32_t)__half_as_ushort(a);
}

// ---------------- merged conversions + gate (one launch) -----------------------
#define T_W1   22528
#define T_W3   45056
#define T_W2   67584
#define T_S1   69120
#define T_S3   70656
#define T_ALL  72192
#define T_GATE (T_ALL + TOK / 8)     // 512 gate blocks appended

__device__ __forceinline__ void cvt_tile(const float* __restrict__ in,
                                         fp16* __restrict__ out,
                                         int K, int N, int kt, int nt) {
    __shared__ float tile[32][33];
    int k0 = kt * 32, n0 = nt * 32;
    int idx = threadIdx.x;
    int tx = idx & 31, ty = idx >> 5;
#pragma unroll
    for (int j = 0; j < 4; j++)
        tile[ty + 8 * j][tx] = in[(size_t)(k0 + ty + 8 * j) * N + (n0 + tx)];
    __syncthreads();
    int nl = idx >> 3, kq = (idx & 7) * 4;
    float v0 = tile[kq + 0][nl], v1 = tile[kq + 1][nl];
    float v2 = tile[kq + 2][nl], v3 = tile[kq + 3][nl];
    uint2 o;
    o.x = pack2(__float2half(v0), __float2half(v1));
    o.y = pack2(__float2half(v2), __float2half(v3));
    *reinterpret_cast<uint2*>(out + (size_t)(n0 + nl) * K + k0 + kq) = o;
}

// gate body: 8 warps per block, one token per warp. Also emits x fp16 copy.
__device__ __forceinline__ void gate_body(const float* __restrict__ x,
                                          const float* __restrict__ gw,
                                          int blk) {
    int tok  = blk * 8 + (threadIdx.x >> 5);
    int lane = threadIdx.x & 31;
    if (tok >= TOK) return;
    const float4* xr = reinterpret_cast<const float4*>(x + (size_t)tok * DIM);
    uint2* xo = reinterpret_cast<uint2*>(g_xh + (size_t)tok * DIM);
    float acc[NEXP];
#pragma unroll
    for (int e = 0; e < NEXP; e++) acc[e] = 0.f;
#pragma unroll
    for (int j = 0; j < 8; j++) {
        int q = lane + j * 32;
        float4 v = xr[q];
        uint2 ph;
        ph.x = pack2(__float2half(v.x), __float2half(v.y));
        ph.y = pack2(__float2half(v.z), __float2half(v.w));
        xo[q] = ph;
        int d = q * 4;
#pragma unroll
        for (int e = 0; e < NEXP; e++) {
            const float* gr = gw + e * DIM + d;
            acc[e] = fmaf(v.x, gr[0], acc[e]);
            acc[e] = fmaf(v.y, gr[1], acc[e]);
            acc[e] = fmaf(v.z, gr[2], acc[e]);
            acc[e] = fmaf(v.w, gr[3], acc[e]);
        }
    }
#pragma unroll
    for (int e = 0; e < NEXP; e++)
#pragma unroll
        for (int off = 16; off > 0; off >>= 1)
            acc[e] += __shfl_xor_sync(0xffffffffu, acc[e], off);
    if (lane == 0) {
        float mx = acc[0];
#pragma unroll
        for (int e = 1; e < NEXP; e++) mx = fmaxf(mx, acc[e]);
        float p[NEXP], s = 0.f;
#pragma unroll
        for (int e = 0; e < NEXP; e++) { p[e] = expf(acc[e] - mx); s += p[e]; }
        float inv = 1.f / s;
#pragma unroll
        for (int e = 0; e < NEXP; e++) p[e] *= inv;
        int i1 = 0;
#pragma unroll
        for (int e = 1; e < NEXP; e++) if (p[e] > p[i1]) i1 = e;
        int i2 = (i1 == 0) ? 1 : 0;
#pragma unroll
        for (int e = 0; e < NEXP; e++) if (e != i1 && p[e] > p[i2]) i2 = e;
        int pos1 = atomicAdd(&g_cnt[i1], 1);
        g_idx[i1 * TOK + pos1] = tok;  g_wgt[i1 * TOK + pos1] = p[i1];
        g_slot[2 * tok] = i1 * TOK + pos1;
        int pos2 = atomicAdd(&g_cnt[i2], 1);
        g_idx[i2 * TOK + pos2] = tok;  g_wgt[i2 * TOK + pos2] = p[i2];
        g_slot[2 * tok + 1] = i2 * TOK + pos2;
    }
}

__global__ void __launch_bounds__(256)
cvt_all_kernel(const float* __restrict__ w1, const float* __restrict__ w3,
               const float* __restrict__ w2, const float* __restrict__ sw1,
               const float* __restrict__ sw3, const float* __restrict__ sw2,
               const float* __restrict__ x,  const float* __restrict__ gw) {
    int t = blockIdx.x;
    if (t < T_W1) {
        int z = t / (32 * 88), r = t % (32 * 88);
        cvt_tile(w1 + (size_t)z * DIM * EHID, g_w1h + (size_t)z * EHID * DIM,
                 DIM, EHID, r % 32, r / 32);
    } else if (t < T_W3) {
        t -= T_W1;
        int z = t / (32 * 88), r = t % (32 * 88);
        cvt_tile(w3 + (size_t)z * DIM * EHID, g_w3h + (size_t)z * EHID * DIM,
                 DIM, EHID, r % 32, r / 32);
    } else if (t < T_W2) {
        t -= T_W3;
        int z = t / (88 * 32), r = t % (88 * 32);
        cvt_tile(w2 + (size_t)z * EHID * DIM, g_w2h + (size_t)z * DIM * EHID,
                 EHID, DIM, r % 88, r / 88);
    } else if (t < T_S1) {
        t -= T_W2;
        cvt_tile(sw1, g_s1h, DIM, SHID, t % 32, t / 32);
    } else if (t < T_S3) {
        t -= T_S1;
        cvt_tile(sw3, g_s3h, DIM, SHID, t % 32, t / 32);
    } else if (t < T_ALL) {
        t -= T_S3;
        cvt_tile(sw2, g_s2h, SHID, DIM, t % 48, t / 48);
    } else {
        gate_body(x, gw, t - T_ALL);
    }
}

// ---------------- GEMM1: fused SwiGLU up-proj (BK=32, 3-stage) ------------------
// grid.z in [0,8]: z<8 routed expert z, z==8 shared. BM=128, BN=64/matrix.
#define G1_S_AH   0
#define G1_S_B1H  5120
#define G1_S_B3H  7680
#define G1_STG    10240
#define G1_SMEM   (3 * G1_STG * 2)   // 61440 B

__global__ void __launch_bounds__(256, 2)
gemm1_kernel() {
    const int K = DIM;
    int z = blockIdx.z;
    bool sh = (z == NEXP);
    int M = sh ? TOK : g_cnt[z];
    int N = sh ? SHID : EHID;
    int rowBlock = blockIdx.y * 128;
    if (rowBlock >= M) return;
    int colBlock = blockIdx.x * 64;
    if (colBlock >= N) return;
    const fp16* B1 = sh ? g_s1h : g_w1h + (size_t)z * EHID * DIM;
    const fp16* B3 = sh ? g_s3h : g_w3h + (size_t)z * EHID * DIM;
    fp16* H        = sh ? g_hsh : g_hh  + (size_t)z * TOK * EHID;

    extern __shared__ __align__(16) fp16 sm1[];
    uint32_t sb0 = smem_u32(sm1);

    int tid = threadIdx.x, lane = tid & 31, warp = tid >> 5;
    int wm = warp >> 2, wn = warp & 3;

    int ra = tid >> 1, ka = (tid & 1) * 16;
    bool aval = (rowBlock + ra) < M;
    int asrc = aval ? (sh ? rowBlock + ra : g_idx[z * TOK + rowBlock + ra]) : 0;
    const fp16* aph = g_xh + (size_t)asrc * K + ka;
    uint32_t adst = (uint32_t)(ra * LDH + ka) * 2;

    int rb = tid >> 2, kb = (tid & 3) * 8;
    const fp16* b1p = B1 + (size_t)(colBlock + rb) * K + kb;
    const fp16* b3p = B3 + (size_t)(colBlock + rb) * K + kb;
    uint32_t bdst = (uint32_t)(rb * LDH + kb) * 2;

    auto load_stage = [&](int s, int k0) {
        uint32_t sb = sb0 + (uint32_t)s * G1_STG * 2;
        cp16(sb + G1_S_AH * 2 + adst,      aph + k0,     aval);
        cp16(sb + G1_S_AH * 2 + adst + 16, aph + k0 + 8, aval);
        cp16(sb + G1_S_B1H * 2 + bdst, b1p + k0, true);
        cp16(sb + G1_S_B3H * 2 + bdst, b3p + k0, true);
    };

    int lrow = lane & 15, lkA = (lane >> 4) * 8;
    uint32_t aOff[4];
#pragma unroll
    for (int mi = 0; mi < 4; mi++) {
        int r = wm * 64 + mi * 16 + lrow;
        aOff[mi] = (uint32_t)(G1_S_AH + r * LDH + lkA) * 2;
    }
    int nloc = (lane & 7) | ((lane & 16) >> 1);
    int lkB  = ((lane >> 3) & 1) * 8;
    uint32_t bRow = (uint32_t)((wn * 16 + nloc) * LDH + lkB) * 2;
    uint32_t b1Off = G1_S_B1H * 2 + bRow;
    uint32_t b3Off = G1_S_B3H * 2 + bRow;

    float acc1[4][2][4], acc3[4][2][4];
#pragma unroll
    for (int i = 0; i < 4; i++)
#pragma unroll
        for (int j = 0; j < 2; j++)
#pragma unroll
            for (int r = 0; r < 4; r++) { acc1[i][j][r] = 0.f; acc3[i][j][r] = 0.f; }

    const int nIter = K / 32;
    load_stage(0, 0);
    CP_COMMIT();
    load_stage(1, 32);
    CP_COMMIT();
    int cur = 0, pre = 2;
    for (int i = 0; i < nIter; i++) {
        if (i < nIter - 1) { CP_WAIT1(); } else { CP_WAIT0(); }
        __syncthreads();
        if (i + 2 < nIter) { load_stage(pre, (i + 2) * 32); CP_COMMIT(); }
        uint32_t sb = sb0 + (uint32_t)cur * G1_STG * 2;
#pragma unroll
        for (int ks = 0; ks < 2; ks++) {
            uint32_t ko = (uint32_t)ks * 32;
            uint32_t ah[4][4];
#pragma unroll
            for (int mi = 0; mi < 4; mi++)
                LDSM4(ah[mi], sb + aOff[mi] + ko);
            uint32_t b1[4], b3[4];
            LDSM4(b1, sb + b1Off + ko);
            LDSM4(b3, sb + b3Off + ko);
#pragma unroll
            for (int mi = 0; mi < 4; mi++)
#pragma unroll
                for (int nf = 0; nf < 2; nf++) {
                    mma_f16(acc1[mi][nf], ah[mi], b1[2*nf], b1[2*nf+1]);
                    mma_f16(acc3[mi][nf], ah[mi], b3[2*nf], b3[2*nf+1]);
                }
        }
        cur = (cur == 2) ? 0 : cur + 1;
        pre = (pre == 2) ? 0 : pre + 1;
    }

    int rr = lane >> 2, cc = (lane & 3) * 2;
#pragma unroll
    for (int mi = 0; mi < 4; mi++) {
        int gmb = rowBlock + wm * 64 + mi * 16 + rr;
#pragma unroll
        for (int nf = 0; nf < 2; nf++) {
            int col = colBlock + wn * 16 + nf * 8 + cc;
#pragma unroll
            for (int hf = 0; hf < 2; hf++) {
                int gm = gmb + hf * 8;
                if (gm < M) {
                    float v1a = acc1[mi][nf][hf*2], v1b = acc1[mi][nf][hf*2+1];
                    float v3a = acc3[mi][nf][hf*2], v3b = acc3[mi][nf][hf*2+1];
                    float h0 = v1a / (1.f + expf(-v1a)) * v3a;
                    float h1 = v1b / (1.f + expf(-v1b)) * v3b;
                    *reinterpret_cast<uint32_t*>(H + (size_t)gm * N + col) =
                        pack2(__float2half(h0), __float2half(h1));
                }
            }
        }
    }
}

// ---------------- GEMM2: down-projection (BN=128, BK=32, 3-stage) ---------------
#define G2_S_A   0
#define G2_S_B   5120
#define G2_STG   10240
#define G2_SMEM  (3 * G2_STG * 2)    // 61440 B

__global__ void __launch_bounds__(256, 2)
gemm2_kernel(float* __restrict__ out) {
    int z = blockIdx.z;
    bool sh = (z == NEXP);
    int M = sh ? TOK : g_cnt[z];
    int K = sh ? SHID : EHID;
    int rowBlock = blockIdx.y * 128;
    if (rowBlock >= M) return;
    int colBlock = blockIdx.x * 128;
    const fp16* A = sh ? g_hsh : g_hh + (size_t)z * TOK * EHID;
    const fp16* B = sh ? g_s2h : g_w2h + (size_t)z * DIM * EHID;
    float* Y      = sh ? out   : g_yp  + (size_t)z * TOK * DIM;

    extern __shared__ __align__(16) fp16 sm2[];
    uint32_t sb0 = smem_u32(sm2);

    int tid = threadIdx.x, lane = tid & 31, warp = tid >> 5;
    int wm = warp >> 2, wn = warp & 3;

    int ra = tid >> 1, ka = (tid & 1) * 16;
    bool aval = (rowBlock + ra) < M;
    const fp16* aph = A + (size_t)(aval ? rowBlock + ra : 0) * K + ka;
    const fp16* bph = B + (size_t)(colBlock + ra) * K + ka;
    uint32_t adst = (uint32_t)(ra * LDH + ka) * 2;

    auto load_stage = [&](int s, int k0) {
        uint32_t sb = sb0 + (uint32_t)s * G2_STG * 2;
        cp16(sb + G2_S_A * 2 + adst,      aph + k0,     aval);
        cp16(sb + G2_S_A * 2 + adst + 16, aph + k0 + 8, aval);
        cp16(sb + G2_S_B * 2 + adst,      bph + k0,     true);
        cp16(sb + G2_S_B * 2 + adst + 16, bph + k0 + 8, true);
    };

    int lrow = lane & 15, lkA = (lane >> 4) * 8;
    uint32_t aOff[4];
#pragma unroll
    for (int mi = 0; mi < 4; mi++) {
        int r = wm * 64 + mi * 16 + lrow;
        aOff[mi] = (uint32_t)(G2_S_A + r * LDH + lkA) * 2;
    }
    int nloc = (lane & 7) | ((lane & 16) >> 1);
    int lkB  = ((lane >> 3) & 1) * 8;
    uint32_t bOff[2];
#pragma unroll
    for (int ng = 0; ng < 2; ng++) {
        int n = wn * 32 + ng * 16 + nloc;
        bOff[ng] = (uint32_t)(G2_S_B + n * LDH + lkB) * 2;
    }

    float acc[4][4][4];
#pragma unroll
    for (int i = 0; i < 4; i++)
#pragma unroll
        for (int j = 0; j < 4; j++)
#pragma unroll
            for (int r = 0; r < 4; r++) acc[i][j][r] = 0.f;

    const int nIter = K / 32;
    load_stage(0, 0);
    CP_COMMIT();
    load_stage(1, 32);
    CP_COMMIT();
    int cur = 0, pre = 2;
    for (int i = 0; i < nIter; i++) {
        if (i < nIter - 1) { CP_WAIT1(); } else { CP_WAIT0(); }
        __syncthreads();
        if (i + 2 < nIter) { load_stage(pre, (i + 2) * 32); CP_COMMIT(); }
        uint32_t sb = sb0 + (uint32_t)cur * G2_STG * 2;
#pragma unroll
        for (int ks = 0; ks < 2; ks++) {
            uint32_t ko = (uint32_t)ks * 32;
            uint32_t ah[4][4];
#pragma unroll
            for (int mi = 0; mi < 4; mi++)
                LDSM4(ah[mi], sb + aOff[mi] + ko);
            uint32_t b[2][4];
#pragma unroll
            for (int ng = 0; ng < 2; ng++)
                LDSM4(b[ng], sb + bOff[ng] + ko);
#pragma unroll
            for (int mi = 0; mi < 4; mi++)
#pragma unroll
                for (int nf = 0; nf < 4; nf++)
                    mma_f16(acc[mi][nf], ah[mi], b[nf >> 1][(nf & 1) * 2],
                            b[nf >> 1][(nf & 1) * 2 + 1]);
        }
        cur = (cur == 2) ? 0 : cur + 1;
        pre = (pre == 2) ? 0 : pre + 1;
    }

    int rr = lane >> 2, cc = (lane & 3) * 2;
#pragma unroll
    for (int mi = 0; mi < 4; mi++) {
        int gmb = rowBlock + wm * 64 + mi * 16 + rr;
#pragma unroll
        for (int hf = 0; hf < 2; hf++) {
            int gm = gmb + hf * 8;
            if (gm < M) {
                float w = sh ? 1.0f : g_wgt[z * TOK + gm];
                float* dst = Y + (size_t)gm * DIM;
#pragma unroll
                for (int nf = 0; nf < 4; nf++) {
                    int col = colBlock + wn * 32 + nf * 8 + cc;
                    float2 v;
                    v.x = w * acc[mi][nf][hf*2];
                    v.y = w * acc[mi][nf][hf*2+1];
                    *reinterpret_cast<float2*>(dst + col) = v;
                }
            }
        }
    }
}

// out[t] += yp[slot0(t)] + yp[slot1(t)]; also re-zeroes g_cnt for the next call
__global__ void combine_kernel(float* __restrict__ out) {
    int t = blockIdx.x;
    int d = threadIdx.x;
    if (t == 0 && d < NEXP) g_cnt[d] = 0;     // reset for next launch/replay
    int s0 = g_slot[2 * t], s1 = g_slot[2 * t + 1];
    float4* o = reinterpret_cast<float4*>(out) + (size_t)t * 256 + d;
    const float4 a  = *o;
    const float4 b0 = reinterpret_cast<const float4*>(g_yp)[(size_t)s0 * 256 + d];
    const float4 b1 = reinterpret_cast<const float4*>(g_yp)[(size_t)s1 * 256 + d];
    float4 r;
    r.x = a.x + (b0.x + b1.x);
    r.y = a.y + (b0.y + b1.y);
    r.z = a.z + (b0.z + b1.z);
    r.w = a.w + (b0.w + b1.w);
    *o = r;
}

// ---------------- launcher -----------------------------------------------------
extern "C" void kernel_launch(void* const* d_in, const int* in_sizes, int n_in,
                              void* d_out, int out_size) {
    const float* x   = (const float*)d_in[0];
    const float* gw  = (const float*)d_in[1];
    const float* w1  = (const float*)d_in[2];
    const float* w2  = (const float*)d_in[3];
    const float* w3  = (const float*)d_in[4];
    const float* sw1 = (const float*)d_in[5];
    const float* sw2 = (const float*)d_in[6];
    const float* sw3 = (const float*)d_in[7];
    float* out = (float*)d_out;
    (void)in_sizes; (void)n_in; (void)out_size;

    cudaFuncSetAttribute(gemm1_kernel, cudaFuncAttributeMaxDynamicSharedMemorySize, G1_SMEM);
    cudaFuncSetAttribute(gemm2_kernel, cudaFuncAttributeMaxDynamicSharedMemorySize, G2_SMEM);

    // weight conversions + gate/top-2 + x fp16 copy, all in one wave
    cvt_all_kernel<<<T_GATE, 256>>>(w1, w3, w2, sw1, sw3, sw2, x, gw);

    // merged up-proj: z<8 routed experts, z==8 shared expert
    gemm1_kernel<<<dim3(EHID / 64, TOK / 128, NEXP + 1), 256, G1_SMEM>>>();
    // merged down-proj: shared writes d_out, routed writes yp partials
    gemm2_kernel<<<dim3(DIM / 128, TOK / 128, NEXP + 1), 256, G2_SMEM>>>(out);

    // combine (+ reset g_cnt for next call)
    combine_kernel<<<TOK, 256>>>(out);
}

// round 15
// speedup vs baseline: 1.4579x; 1.0927x over previous
#include <cuda_runtime.h>
#include <cuda_fp16.h>
#include <math.h>
#include <stdint.h>

#define TOK   4096
#define DIM   1024
#define NEXP  8
#define EHID  2816
#define SHID  1536
#define LDH   40      // A-tile smem row stride (halves): 32 data + 8 pad
#define LDB1  72      // gemm1 B-tile row stride (halves): 64 data + 8 pad
#define LDB2  136     // gemm2 B-tile row stride (halves): 128 data + 8 pad

typedef __half fp16;

// ---------------- scratch (device globals; zero-initialized at load) ---------
__device__ fp16  g_xh [(size_t)TOK*DIM];
__device__ fp16  g_w1h[(size_t)NEXP*DIM*EHID];   // native layout [e][K=DIM][N=EHID]
__device__ fp16  g_w3h[(size_t)NEXP*DIM*EHID];
__device__ fp16  g_w2h[(size_t)NEXP*EHID*DIM];   // native [e][K=EHID][N=DIM]
__device__ fp16  g_s1h[(size_t)DIM*SHID];        // native [K=DIM][N=SHID]
__device__ fp16  g_s3h[(size_t)DIM*SHID];
__device__ fp16  g_s2h[(size_t)SHID*DIM];        // native [K=SHID][N=DIM]
__device__ fp16  g_hh [(size_t)NEXP*TOK*EHID];   // routed hidden (row-major K)
__device__ fp16  g_hsh[(size_t)TOK*SHID];        // shared hidden
__device__ float g_yp [(size_t)NEXP*TOK*DIM];
__device__ int   g_cnt[NEXP];                    // zeroed by combine_kernel tail
__device__ int   g_idx[NEXP*TOK];
__device__ float g_wgt[NEXP*TOK];
__device__ int   g_slot[TOK*2];

// ---------------- helpers ----------------------------------------------------
__device__ __forceinline__ uint32_t smem_u32(const void* p) {
    uint32_t a;
    asm("{ .reg .u64 t; cvta.to.shared.u64 t, %1; cvt.u32.u64 %0, t; }"
        : "=r"(a) : "l"(p));
    return a;
}
__device__ __forceinline__ void cp16(uint32_t saddr, const void* g, bool valid) {
    int sz = valid ? 16 : 0;
    asm volatile("cp.async.cg.shared.global [%0], [%1], 16, %2;"
                 :: "r"(saddr), "l"(g), "r"(sz));
}
#define CP_COMMIT() asm volatile("cp.async.commit_group;")
#define CP_WAIT1()  asm volatile("cp.async.wait_group 1;")
#define CP_WAIT0()  asm volatile("cp.async.wait_group 0;")

#define LDSM4(r, addr) \
    asm volatile("ldmatrix.sync.aligned.m8n8.x4.shared.b16 {%0,%1,%2,%3}, [%4];" \
        : "=r"((r)[0]), "=r"((r)[1]), "=r"((r)[2]), "=r"((r)[3]) : "r"(addr))

#define LDSM4T(r, addr) \
    asm volatile("ldmatrix.sync.aligned.m8n8.x4.trans.shared.b16 {%0,%1,%2,%3}, [%4];" \
        : "=r"((r)[0]), "=r"((r)[1]), "=r"((r)[2]), "=r"((r)[3]) : "r"(addr))

__device__ __forceinline__ void mma_f16(float d[4], const uint32_t a[4],
                                        uint32_t b0, uint32_t b1) {
    asm volatile(
        "mma.sync.aligned.m16n8k16.row.col.f32.f16.f16.f32 "
        "{%0,%1,%2,%3},{%4,%5,%6,%7},{%8,%9},{%0,%1,%2,%3};"
        : "+f"(d[0]), "+f"(d[1]), "+f"(d[2]), "+f"(d[3])
        : "r"(a[0]), "r"(a[1]), "r"(a[2]), "r"(a[3]), "r"(b0), "r"(b1));
}

__device__ __forceinline__ uint32_t pack2(fp16 a, fp16 b) {
    return ((uint32_t)__half_as_ushort(b) << 16) | (uint32_t)__half_as_ushort(a);
}

// ---------------- streaming conversions + gate (one launch) --------------------
// 8192 elements per block (256 thr x 8 float4). No transpose needed anymore.
#define BW1  2816            // 23,068,672 / 8192
#define BSH  192             // 1,572,864 / 8192
#define C_W1 BW1
#define C_W3 (C_W1 + BW1)
#define C_W2 (C_W3 + BW1)
#define C_S1 (C_W2 + BSH)
#define C_S3 (C_S1 + BSH)
#define C_S2 (C_S3 + BSH)
#define C_GATE (C_S2 + TOK / 8)

__device__ __forceinline__ void cvt_seg(const float* __restrict__ in,
                                        fp16* __restrict__ out, int blk) {
    size_t base4 = (size_t)blk * 2048 + threadIdx.x;     // float4 index
    const float4* src = reinterpret_cast<const float4*>(in) + base4;
    uint2* dst = reinterpret_cast<uint2*>(out) + base4;
#pragma unroll
    for (int i = 0; i < 8; i++) {
        float4 v = src[(size_t)i * 256];
        uint2 o;
        o.x = pack2(__float2half(v.x), __float2half(v.y));
        o.y = pack2(__float2half(v.z), __float2half(v.w));
        dst[(size_t)i * 256] = o;
    }
}

__device__ __forceinline__ void gate_body(const float* __restrict__ x,
                                          const float* __restrict__ gw,
                                          int blk) {
    int tok  = blk * 8 + (threadIdx.x >> 5);
    int lane = threadIdx.x & 31;
    if (tok >= TOK) return;
    const float4* xr = reinterpret_cast<const float4*>(x + (size_t)tok * DIM);
    uint2* xo = reinterpret_cast<uint2*>(g_xh + (size_t)tok * DIM);
    float acc[NEXP];
#pragma unroll
    for (int e = 0; e < NEXP; e++) acc[e] = 0.f;
#pragma unroll
    for (int j = 0; j < 8; j++) {
        int q = lane + j * 32;
        float4 v = xr[q];
        uint2 ph;
        ph.x = pack2(__float2half(v.x), __float2half(v.y));
        ph.y = pack2(__float2half(v.z), __float2half(v.w));
        xo[q] = ph;
        int d = q * 4;
#pragma unroll
        for (int e = 0; e < NEXP; e++) {
            const float* gr = gw + e * DIM + d;
            acc[e] = fmaf(v.x, gr[0], acc[e]);
            acc[e] = fmaf(v.y, gr[1], acc[e]);
            acc[e] = fmaf(v.z, gr[2], acc[e]);
            acc[e] = fmaf(v.w, gr[3], acc[e]);
        }
    }
#pragma unroll
    for (int e = 0; e < NEXP; e++)
#pragma unroll
        for (int off = 16; off > 0; off >>= 1)
            acc[e] += __shfl_xor_sync(0xffffffffu, acc[e], off);
    if (lane == 0) {
        float mx = acc[0];
#pragma unroll
        for (int e = 1; e < NEXP; e++) mx = fmaxf(mx, acc[e]);
        float p[NEXP], s = 0.f;
#pragma unroll
        for (int e = 0; e < NEXP; e++) { p[e] = expf(acc[e] - mx); s += p[e]; }
        float inv = 1.f / s;
#pragma unroll
        for (int e = 0; e < NEXP; e++) p[e] *= inv;
        int i1 = 0;
#pragma unroll
        for (int e = 1; e < NEXP; e++) if (p[e] > p[i1]) i1 = e;
        int i2 = (i1 == 0) ? 1 : 0;
#pragma unroll
        for (int e = 0; e < NEXP; e++) if (e != i1 && p[e] > p[i2]) i2 = e;
        int pos1 = atomicAdd(&g_cnt[i1], 1);
        g_idx[i1 * TOK + pos1] = tok;  g_wgt[i1 * TOK + pos1] = p[i1];
        g_slot[2 * tok] = i1 * TOK + pos1;
        int pos2 = atomicAdd(&g_cnt[i2], 1);
        g_idx[i2 * TOK + pos2] = tok;  g_wgt[i2 * TOK + pos2] = p[i2];
        g_slot[2 * tok + 1] = i2 * TOK + pos2;
    }
}

__global__ void __launch_bounds__(256)
cvt_all_kernel(const float* __restrict__ w1, const float* __restrict__ w3,
               const float* __restrict__ w2, const float* __restrict__ sw1,
               const float* __restrict__ sw3, const float* __restrict__ sw2,
               const float* __restrict__ x,  const float* __restrict__ gw) {
    int t = blockIdx.x;
    if      (t < C_W1) cvt_seg(w1,  g_w1h, t);
    else if (t < C_W3) cvt_seg(w3,  g_w3h, t - C_W1);
    else if (t < C_W2) cvt_seg(w2,  g_w2h, t - C_W3);
    else if (t < C_S1) cvt_seg(sw1, g_s1h, t - C_W2);
    else if (t < C_S3) cvt_seg(sw3, g_s3h, t - C_S1);
    else if (t < C_S2) cvt_seg(sw2, g_s2h, t - C_S3);
    else               gate_body(x, gw, t - C_S2);
}

// ---------------- GEMM1: fused SwiGLU up-proj (trans-B, BK=32, 3-stage) ---------
// Stage (halves): A[128*LDH]=5120, B1[32*LDB1]=2304 @5120, B3 @7424. STG=9728.
#define G1_S_A   0
#define G1_S_B1  5120
#define G1_S_B3  7424
#define G1_STG   9728
#define G1_SMEM  (3 * G1_STG * 2)    // 58368 B

__global__ void __launch_bounds__(256, 2)
gemm1_kernel() {
    const int K = DIM;
    int z = blockIdx.z;
    bool sh = (z == NEXP);
    int M = sh ? TOK : g_cnt[z];
    int N = sh ? SHID : EHID;
    int rowBlock = blockIdx.y * 128;
    if (rowBlock >= M) return;
    int colBlock = blockIdx.x * 64;
    if (colBlock >= N) return;
    const fp16* B1 = sh ? g_s1h : g_w1h + (size_t)z * DIM * EHID;
    const fp16* B3 = sh ? g_s3h : g_w3h + (size_t)z * DIM * EHID;
    fp16* H        = sh ? g_hsh : g_hh  + (size_t)z * TOK * EHID;

    extern __shared__ __align__(16) fp16 sm1[];
    uint32_t sb0 = smem_u32(sm1);

    int tid = threadIdx.x, lane = tid & 31, warp = tid >> 5;
    int wm = warp >> 2, wn = warp & 3;

    // A: 2 thr/row, 16 halves each (unchanged)
    int ra = tid >> 1, ka = (tid & 1) * 16;
    bool aval = (rowBlock + ra) < M;
    int asrc = aval ? (sh ? rowBlock + ra : g_idx[z * TOK + rowBlock + ra]) : 0;
    const fp16* aph = g_xh + (size_t)asrc * K + ka;
    uint32_t adst = (uint32_t)(ra * LDH + ka) * 2;

    // B: native [k][n]; tile = 32 k-rows x 64 n. thread: row=tid>>3, chunk=tid&7
    int brow = tid >> 3, bch = (tid & 7) * 8;
    const fp16* b1p = B1 + (size_t)brow * N + colBlock + bch;
    const fp16* b3p = B3 + (size_t)brow * N + colBlock + bch;
    uint32_t b1dst = (uint32_t)(G1_S_B1 + brow * LDB1 + bch) * 2;
    uint32_t b3dst = (uint32_t)(G1_S_B3 + brow * LDB1 + bch) * 2;

    auto load_stage = [&](int s, int k0) {
        uint32_t sb = sb0 + (uint32_t)s * G1_STG * 2;
        cp16(sb + G1_S_A * 2 + adst,      aph + k0,     aval);
        cp16(sb + G1_S_A * 2 + adst + 16, aph + k0 + 8, aval);
        size_t ko = (size_t)k0 * N;
        cp16(sb + b1dst, b1p + ko, true);
        cp16(sb + b3dst, b3p + ko, true);
    };

    int lrow = lane & 15, lkA = (lane >> 4) * 8;
    uint32_t aOff[4];
#pragma unroll
    for (int mi = 0; mi < 4; mi++) {
        int r = wm * 64 + mi * 16 + lrow;
        aOff[mi] = (uint32_t)(G1_S_A + r * LDH + lkA) * 2;
    }
    // trans-B addresses: group g=lane>>3: k=(g&1)*8+r, n=+(g>>1)*8
    int bg = lane >> 3, br = lane & 7;
    uint32_t bRowT = (uint32_t)(((bg & 1) * 8 + br) * LDB1 + wn * 16 + (bg >> 1) * 8) * 2;
    uint32_t b1OffT = G1_S_B1 * 2 + bRowT;
    uint32_t b3OffT = G1_S_B3 * 2 + bRowT;
    const uint32_t ksB = 16 * LDB1 * 2;     // k-step byte offset in B tile

    float acc1[4][2][4], acc3[4][2][4];
#pragma unroll
    for (int i = 0; i < 4; i++)
#pragma unroll
        for (int j = 0; j < 2; j++)
#pragma unroll
            for (int r = 0; r < 4; r++) { acc1[i][j][r] = 0.f; acc3[i][j][r] = 0.f; }

    const int nIter = K / 32;
    load_stage(0, 0);
    CP_COMMIT();
    load_stage(1, 32);
    CP_COMMIT();
    int cur = 0, pre = 2;
    for (int i = 0; i < nIter; i++) {
        if (i < nIter - 1) { CP_WAIT1(); } else { CP_WAIT0(); }
        __syncthreads();
        if (i + 2 < nIter) { load_stage(pre, (i + 2) * 32); CP_COMMIT(); }
        uint32_t sb = sb0 + (uint32_t)cur * G1_STG * 2;
#pragma unroll
        for (int ks = 0; ks < 2; ks++) {
            uint32_t koA = (uint32_t)ks * 32;
            uint32_t koB = (uint32_t)ks * ksB;
            uint32_t ah[4][4];
#pragma unroll
            for (int mi = 0; mi < 4; mi++)
                LDSM4(ah[mi], sb + aOff[mi] + koA);
            uint32_t b1[4], b3[4];
            LDSM4T(b1, sb + b1OffT + koB);
            LDSM4T(b3, sb + b3OffT + koB);
#pragma unroll
            for (int mi = 0; mi < 4; mi++)
#pragma unroll
                for (int nf = 0; nf < 2; nf++) {
                    mma_f16(acc1[mi][nf], ah[mi], b1[2*nf], b1[2*nf+1]);
                    mma_f16(acc3[mi][nf], ah[mi], b3[2*nf], b3[2*nf+1]);
                }
        }
        cur = (cur == 2) ? 0 : cur + 1;
        pre = (pre == 2) ? 0 : pre + 1;
    }

    int rr = lane >> 2, cc = (lane & 3) * 2;
#pragma unroll
    for (int mi = 0; mi < 4; mi++) {
        int gmb = rowBlock + wm * 64 + mi * 16 + rr;
#pragma unroll
        for (int nf = 0; nf < 2; nf++) {
            int col = colBlock + wn * 16 + nf * 8 + cc;
#pragma unroll
            for (int hf = 0; hf < 2; hf++) {
                int gm = gmb + hf * 8;
                if (gm < M) {
                    float v1a = acc1[mi][nf][hf*2], v1b = acc1[mi][nf][hf*2+1];
                    float v3a = acc3[mi][nf][hf*2], v3b = acc3[mi][nf][hf*2+1];
                    float h0 = v1a / (1.f + expf(-v1a)) * v3a;
                    float h1 = v1b / (1.f + expf(-v1b)) * v3b;
                    *reinterpret_cast<uint32_t*>(H + (size_t)gm * N + col) =
                        pack2(__float2half(h0), __float2half(h1));
                }
            }
        }
    }
}

// ---------------- GEMM2: down-proj (trans-B, BN=128, BK=32, 3-stage) ------------
// Stage (halves): A[128*LDH]=5120, B[32*LDB2]=4352 @5120. STG=9472.
#define G2_S_A   0
#define G2_S_B   5120
#define G2_STG   9472
#define G2_SMEM  (3 * G2_STG * 2)    // 56832 B

__global__ void __launch_bounds__(256, 2)
gemm2_kernel(float* __restrict__ out) {
    int z = blockIdx.z;
    bool sh = (z == NEXP);
    int M = sh ? TOK : g_cnt[z];
    int K = sh ? SHID : EHID;
    int rowBlock = blockIdx.y * 128;
    if (rowBlock >= M) return;
    int colBlock = blockIdx.x * 128;
    const fp16* A = sh ? g_hsh : g_hh + (size_t)z * TOK * EHID;
    const fp16* B = sh ? g_s2h : g_w2h + (size_t)z * EHID * DIM;
    float* Y      = sh ? out   : g_yp  + (size_t)z * TOK * DIM;

    extern __shared__ __align__(16) fp16 sm2[];
    uint32_t sb0 = smem_u32(sm2);

    int tid = threadIdx.x, lane = tid & 31, warp = tid >> 5;
    int wm = warp >> 2, wn = warp & 3;

    int ra = tid >> 1, ka = (tid & 1) * 16;
    bool aval = (rowBlock + ra) < M;
    const fp16* aph = A + (size_t)(aval ? rowBlock + ra : 0) * K + ka;
    uint32_t adst = (uint32_t)(ra * LDH + ka) * 2;

    // B native [k][DIM]: tile 32 k-rows x 128 n; thread: row=tid>>3, chunks c, c+8
    int brow = tid >> 3, bch = (tid & 7) * 8;
    const fp16* bp = B + (size_t)brow * DIM + colBlock + bch;
    uint32_t bdst = (uint32_t)(G2_S_B + brow * LDB2 + bch) * 2;

    auto load_stage = [&](int s, int k0) {
        uint32_t sb = sb0 + (uint32_t)s * G2_STG * 2;
        cp16(sb + G2_S_A * 2 + adst,      aph + k0,     aval);
        cp16(sb + G2_S_A * 2 + adst + 16, aph + k0 + 8, aval);
        size_t ko = (size_t)k0 * DIM;
        cp16(sb + bdst,       bp + ko,      true);
        cp16(sb + bdst + 128, bp + ko + 64, true);   // chunk c+8 (64 halves)
    };

    int lrow = lane & 15, lkA = (lane >> 4) * 8;
    uint32_t aOff[4];
#pragma unroll
    for (int mi = 0; mi < 4; mi++) {
        int r = wm * 64 + mi * 16 + lrow;
        aOff[mi] = (uint32_t)(G2_S_A + r * LDH + lkA) * 2;
    }
    int bg = lane >> 3, br = lane & 7;
    uint32_t bOffT[2];
#pragma unroll
    for (int ng = 0; ng < 2; ng++) {
        int n = wn * 32 + ng * 16 + (bg >> 1) * 8;
        bOffT[ng] = (uint32_t)(G2_S_B + ((bg & 1) * 8 + br) * LDB2 + n) * 2;
    }
    const uint32_t ksB = 16 * LDB2 * 2;

    float acc[4][4][4];
#pragma unroll
    for (int i = 0; i < 4; i++)
#pragma unroll
        for (int j = 0; j < 4; j++)
#pragma unroll
            for (int r = 0; r < 4; r++) acc[i][j][r] = 0.f;

    const int nIter = K / 32;
    load_stage(0, 0);
    CP_COMMIT();
    load_stage(1, 32);
    CP_COMMIT();
    int cur = 0, pre = 2;
    for (int i = 0; i < nIter; i++) {
        if (i < nIter - 1) { CP_WAIT1(); } else { CP_WAIT0(); }
        __syncthreads();
        if (i + 2 < nIter) { load_stage(pre, (i + 2) * 32); CP_COMMIT(); }
        uint32_t sb = sb0 + (uint32_t)cur * G2_STG * 2;
#pragma unroll
        for (int ks = 0; ks < 2; ks++) {
            uint32_t koA = (uint32_t)ks * 32;
            uint32_t koB = (uint32_t)ks * ksB;
            uint32_t ah[4][4];
#pragma unroll
            for (int mi = 0; mi < 4; mi++)
                LDSM4(ah[mi], sb + aOff[mi] + koA);
            uint32_t b[2][4];
#pragma unroll
            for (int ng = 0; ng < 2; ng++)
                LDSM4T(b[ng], sb + bOffT[ng] + koB);
#pragma unroll
            for (int mi = 0; mi < 4; mi++)
#pragma unroll
                for (int nf = 0; nf < 4; nf++)
                    mma_f16(acc[mi][nf], ah[mi], b[nf >> 1][(nf & 1) * 2],
                            b[nf >> 1][(nf & 1) * 2 + 1]);
        }
        cur = (cur == 2) ? 0 : cur + 1;
        pre = (pre == 2) ? 0 : pre + 1;
    }

    int rr = lane >> 2, cc = (lane & 3) * 2;
#pragma unroll
    for (int mi = 0; mi < 4; mi++) {
        int gmb = rowBlock + wm * 64 + mi * 16 + rr;
#pragma unroll
        for (int hf = 0; hf < 2; hf++) {
            int gm = gmb + hf * 8;
            if (gm < M) {
                float w = sh ? 1.0f : g_wgt[z * TOK + gm];
                float* dst = Y + (size_t)gm * DIM;
#pragma unroll
                for (int nf = 0; nf < 4; nf++) {
                    int col = colBlock + wn * 32 + nf * 8 + cc;
                    float2 v;
                    v.x = w * acc[mi][nf][hf*2];
                    v.y = w * acc[mi][nf][hf*2+1];
                    *reinterpret_cast<float2*>(dst + col) = v;
                }
            }
        }
    }
}

// out[t] += yp[slot0(t)] + yp[slot1(t)]; also re-zeroes g_cnt for the next call
__global__ void combine_kernel(float* __restrict__ out) {
    int t = blockIdx.x;
    int d = threadIdx.x;
    if (t == 0 && d < NEXP) g_cnt[d] = 0;
    int s0 = g_slot[2 * t], s1 = g_slot[2 * t + 1];
    float4* o = reinterpret_cast<float4*>(out) + (size_t)t * 256 + d;
    const float4 a  = *o;
    const float4 b0 = reinterpret_cast<const float4*>(g_yp)[(size_t)s0 * 256 + d];
    const float4 b1 = reinterpret_cast<const float4*>(g_yp)[(size_t)s1 * 256 + d];
    float4 r;
    r.x = a.x + (b0.x + b1.x);
    r.y = a.y + (b0.y + b1.y);
    r.z = a.z + (b0.z + b1.z);
    r.w = a.w + (b0.w + b1.w);
    *o = r;
}

// ---------------- launcher -----------------------------------------------------
extern "C" void kernel_launch(void* const* d_in, const int* in_sizes, int n_in,
                              void* d_out, int out_size) {
    const float* x   = (const float*)d_in[0];
    const float* gw  = (const float*)d_in[1];
    const float* w1  = (const float*)d_in[2];
    const float* w2  = (const float*)d_in[3];
    const float* w3  = (const float*)d_in[4];
    const float* sw1 = (const float*)d_in[5];
    const float* sw2 = (const float*)d_in[6];
    const float* sw3 = (const float*)d_in[7];
    float* out = (float*)d_out;
    (void)in_sizes; (void)n_in; (void)out_size;

    cudaFuncSetAttribute(gemm1_kernel, cudaFuncAttributeMaxDynamicSharedMemorySize, G1_SMEM);
    cudaFuncSetAttribute(gemm2_kernel, cudaFuncAttributeMaxDynamicSharedMemorySize, G2_SMEM);

    // streaming weight conversion (no transpose) + gate/top-2 + x fp16 copy
    cvt_all_kernel<<<C_GATE, 256>>>(w1, w3, w2, sw1, sw3, sw2, x, gw);

    // merged up-proj: z<8 routed experts, z==8 shared expert
    gemm1_kernel<<<dim3(EHID / 64, TOK / 128, NEXP + 1), 256, G1_SMEM>>>();
    // merged down-proj: shared writes d_out, routed writes yp partials
    gemm2_kernel<<<dim3(DIM / 128, TOK / 128, NEXP + 1), 256, G2_SMEM>>>(out);

    // combine (+ reset g_cnt for next call)
    combine_kernel<<<TOK, 256>>>(out);
}

// round 16
// speedup vs baseline: 1.4662x; 1.0057x over previous
#include <cuda_runtime.h>
#include <cuda_fp16.h>
#include <math.h>
#include <stdint.h>

#define TOK   4096
#define DIM   1024
#define NEXP  8
#define EHID  2816
#define SHID  1536
#define LDH   40      // A-tile smem row stride (halves): 32 data + 8 pad
#define LDB1  72      // gemm1 B-tile row stride (halves): 64 data + 8 pad
#define LDB2  136     // gemm2 B-tile row stride (halves): 128 data + 8 pad

typedef __half fp16;

// ---------------- scratch (device globals; zero-initialized at load) ---------
__device__ fp16  g_xh [(size_t)TOK*DIM];
__device__ fp16  g_w1h[(size_t)NEXP*DIM*EHID];   // native layout [e][K=DIM][N=EHID]
__device__ fp16  g_w3h[(size_t)NEXP*DIM*EHID];
__device__ fp16  g_w2h[(size_t)NEXP*EHID*DIM];   // native [e][K=EHID][N=DIM]
__device__ fp16  g_s1h[(size_t)DIM*SHID];
__device__ fp16  g_s3h[(size_t)DIM*SHID];
__device__ fp16  g_s2h[(size_t)SHID*DIM];
__device__ fp16  g_hh [(size_t)NEXP*TOK*EHID];
__device__ fp16  g_hsh[(size_t)TOK*SHID];
__device__ float g_yp [(size_t)NEXP*TOK*DIM];
__device__ int   g_cnt[NEXP];                    // zeroed by combine_kernel tail
__device__ int   g_idx[NEXP*TOK];
__device__ float g_wgt[NEXP*TOK];
__device__ int   g_slot[TOK*2];

// ---------------- helpers ----------------------------------------------------
__device__ __forceinline__ uint32_t smem_u32(const void* p) {
    uint32_t a;
    asm("{ .reg .u64 t; cvta.to.shared.u64 t, %1; cvt.u32.u64 %0, t; }"
        : "=r"(a) : "l"(p));
    return a;
}
__device__ __forceinline__ void cp16(uint32_t saddr, const void* g, bool valid) {
    int sz = valid ? 16 : 0;
    asm volatile("cp.async.cg.shared.global [%0], [%1], 16, %2;"
                 :: "r"(saddr), "l"(g), "r"(sz));
}
#define CP_COMMIT() asm volatile("cp.async.commit_group;")
#define CP_WAIT0()  asm volatile("cp.async.wait_group 0;")

#define LDSM4(r, addr) \
    asm volatile("ldmatrix.sync.aligned.m8n8.x4.shared.b16 {%0,%1,%2,%3}, [%4];" \
        : "=r"((r)[0]), "=r"((r)[1]), "=r"((r)[2]), "=r"((r)[3]) : "r"(addr))

#define LDSM4T(r, addr) \
    asm volatile("ldmatrix.sync.aligned.m8n8.x4.trans.shared.b16 {%0,%1,%2,%3}, [%4];" \
        : "=r"((r)[0]), "=r"((r)[1]), "=r"((r)[2]), "=r"((r)[3]) : "r"(addr))

__device__ __forceinline__ void mma_f16(float d[4], const uint32_t a[4],
                                        uint32_t b0, uint32_t b1) {
    asm volatile(
        "mma.sync.aligned.m16n8k16.row.col.f32.f16.f16.f32 "
        "{%0,%1,%2,%3},{%4,%5,%6,%7},{%8,%9},{%0,%1,%2,%3};"
        : "+f"(d[0]), "+f"(d[1]), "+f"(d[2]), "+f"(d[3])
        : "r"(a[0]), "r"(a[1]), "r"(a[2]), "r"(a[3]), "r"(b0), "r"(b1));
}

__device__ __forceinline__ uint32_t pack2(fp16 a, fp16 b) {
    return ((uint32_t)__half_as_ushort(b) << 16) | (uint32_t)__half_as_ushort(a);
}

// ---------------- streaming conversions + gate (one launch) --------------------
#define BW1  2816
#define BSH  192
#define C_W1 BW1
#define C_W3 (C_W1 + BW1)
#define C_W2 (C_W3 + BW1)
#define C_S1 (C_W2 + BSH)
#define C_S3 (C_S1 + BSH)
#define C_S2 (C_S3 + BSH)
#define C_GATE (C_S2 + TOK / 8)

__device__ __forceinline__ void cvt_seg(const float* __restrict__ in,
                                        fp16* __restrict__ out, int blk) {
    size_t base4 = (size_t)blk * 2048 + threadIdx.x;
    const float4* src = reinterpret_cast<const float4*>(in) + base4;
    uint2* dst = reinterpret_cast<uint2*>(out) + base4;
#pragma unroll
    for (int i = 0; i < 8; i++) {
        float4 v = src[(size_t)i * 256];
        uint2 o;
        o.x = pack2(__float2half(v.x), __float2half(v.y));
        o.y = pack2(__float2half(v.z), __float2half(v.w));
        dst[(size_t)i * 256] = o;
    }
}

__device__ __forceinline__ void gate_body(const float* __restrict__ x,
                                          const float* __restrict__ gw,
                                          int blk) {
    int tok  = blk * 8 + (threadIdx.x >> 5);
    int lane = threadIdx.x & 31;
    if (tok >= TOK) return;
    const float4* xr = reinterpret_cast<const float4*>(x + (size_t)tok * DIM);
    uint2* xo = reinterpret_cast<uint2*>(g_xh + (size_t)tok * DIM);
    float acc[NEXP];
#pragma unroll
    for (int e = 0; e < NEXP; e++) acc[e] = 0.f;
#pragma unroll
    for (int j = 0; j < 8; j++) {
        int q = lane + j * 32;
        float4 v = xr[q];
        uint2 ph;
        ph.x = pack2(__float2half(v.x), __float2half(v.y));
        ph.y = pack2(__float2half(v.z), __float2half(v.w));
        xo[q] = ph;
        int d = q * 4;
#pragma unroll
        for (int e = 0; e < NEXP; e++) {
            const float* gr = gw + e * DIM + d;
            acc[e] = fmaf(v.x, gr[0], acc[e]);
            acc[e] = fmaf(v.y, gr[1], acc[e]);
            acc[e] = fmaf(v.z, gr[2], acc[e]);
            acc[e] = fmaf(v.w, gr[3], acc[e]);
        }
    }
#pragma unroll
    for (int e = 0; e < NEXP; e++)
#pragma unroll
        for (int off = 16; off > 0; off >>= 1)
            acc[e] += __shfl_xor_sync(0xffffffffu, acc[e], off);
    if (lane == 0) {
        float mx = acc[0];
#pragma unroll
        for (int e = 1; e < NEXP; e++) mx = fmaxf(mx, acc[e]);
        float p[NEXP], s = 0.f;
#pragma unroll
        for (int e = 0; e < NEXP; e++) { p[e] = expf(acc[e] - mx); s += p[e]; }
        float inv = 1.f / s;
#pragma unroll
        for (int e = 0; e < NEXP; e++) p[e] *= inv;
        int i1 = 0;
#pragma unroll
        for (int e = 1; e < NEXP; e++) if (p[e] > p[i1]) i1 = e;
        int i2 = (i1 == 0) ? 1 : 0;
#pragma unroll
        for (int e = 0; e < NEXP; e++) if (e != i1 && p[e] > p[i2]) i2 = e;
        int pos1 = atomicAdd(&g_cnt[i1], 1);
        g_idx[i1 * TOK + pos1] = tok;  g_wgt[i1 * TOK + pos1] = p[i1];
        g_slot[2 * tok] = i1 * TOK + pos1;
        int pos2 = atomicAdd(&g_cnt[i2], 1);
        g_idx[i2 * TOK + pos2] = tok;  g_wgt[i2 * TOK + pos2] = p[i2];
        g_slot[2 * tok + 1] = i2 * TOK + pos2;
    }
}

__global__ void __launch_bounds__(256)
cvt_all_kernel(const float* __restrict__ w1, const float* __restrict__ w3,
               const float* __restrict__ w2, const float* __restrict__ sw1,
               const float* __restrict__ sw3, const float* __restrict__ sw2,
               const float* __restrict__ x,  const float* __restrict__ gw) {
    int t = blockIdx.x;
    if      (t < C_W1) cvt_seg(w1,  g_w1h, t);
    else if (t < C_W3) cvt_seg(w3,  g_w3h, t - C_W1);
    else if (t < C_W2) cvt_seg(w2,  g_w2h, t - C_W3);
    else if (t < C_S1) cvt_seg(sw1, g_s1h, t - C_W2);
    else if (t < C_S3) cvt_seg(sw3, g_s3h, t - C_S1);
    else if (t < C_S2) cvt_seg(sw2, g_s2h, t - C_S3);
    else               gate_body(x, gw, t - C_S2);
}

// ---------------- GEMM1: fused SwiGLU up-proj (trans-B, 4-stage pairs) ----------
#define G1_S_A   0
#define G1_S_B1  5120
#define G1_S_B3  7424
#define G1_STG   9728
#define G1_SMEM  (4 * G1_STG * 2)    // 77824 B

__global__ void __launch_bounds__(256, 2)
gemm1_kernel() {
    const int K = DIM;
    int z = blockIdx.z;
    bool sh = (z == NEXP);
    int M = sh ? TOK : g_cnt[z];
    int N = sh ? SHID : EHID;
    int rowBlock = blockIdx.y * 128;
    if (rowBlock >= M) return;
    int colBlock = blockIdx.x * 64;
    if (colBlock >= N) return;
    const fp16* B1 = sh ? g_s1h : g_w1h + (size_t)z * DIM * EHID;
    const fp16* B3 = sh ? g_s3h : g_w3h + (size_t)z * DIM * EHID;
    fp16* H        = sh ? g_hsh : g_hh  + (size_t)z * TOK * EHID;

    extern __shared__ __align__(16) fp16 sm1[];
    uint32_t sb0 = smem_u32(sm1);

    int tid = threadIdx.x, lane = tid & 31, warp = tid >> 5;
    int wm = warp >> 2, wn = warp & 3;

    int ra = tid >> 1, ka = (tid & 1) * 16;
    bool aval = (rowBlock + ra) < M;
    int asrc = aval ? (sh ? rowBlock + ra : g_idx[z * TOK + rowBlock + ra]) : 0;
    const fp16* aph = g_xh + (size_t)asrc * K + ka;
    uint32_t adst = (uint32_t)(ra * LDH + ka) * 2;

    int brow = tid >> 3, bch = (tid & 7) * 8;
    const fp16* b1p = B1 + (size_t)brow * N + colBlock + bch;
    const fp16* b3p = B3 + (size_t)brow * N + colBlock + bch;
    uint32_t b1dst = (uint32_t)(G1_S_B1 + brow * LDB1 + bch) * 2;
    uint32_t b3dst = (uint32_t)(G1_S_B3 + brow * LDB1 + bch) * 2;

    auto load_stage = [&](int s, int k0) {
        uint32_t sb = sb0 + (uint32_t)s * G1_STG * 2;
        cp16(sb + G1_S_A * 2 + adst,      aph + k0,     aval);
        cp16(sb + G1_S_A * 2 + adst + 16, aph + k0 + 8, aval);
        size_t ko = (size_t)k0 * N;
        cp16(sb + b1dst, b1p + ko, true);
        cp16(sb + b3dst, b3p + ko, true);
    };

    int lrow = lane & 15, lkA = (lane >> 4) * 8;
    uint32_t aOff[4];
#pragma unroll
    for (int mi = 0; mi < 4; mi++) {
        int r = wm * 64 + mi * 16 + lrow;
        aOff[mi] = (uint32_t)(G1_S_A + r * LDH + lkA) * 2;
    }
    int bg = lane >> 3, br = lane & 7;
    uint32_t bRowT = (uint32_t)(((bg & 1) * 8 + br) * LDB1 + wn * 16 + (bg >> 1) * 8) * 2;
    uint32_t b1OffT = G1_S_B1 * 2 + bRowT;
    uint32_t b3OffT = G1_S_B3 * 2 + bRowT;
    const uint32_t ksB = 16 * LDB1 * 2;

    float acc1[4][2][4], acc3[4][2][4];
#pragma unroll
    for (int i = 0; i < 4; i++)
#pragma unroll
        for (int j = 0; j < 2; j++)
#pragma unroll
            for (int r = 0; r < 4; r++) { acc1[i][j][r] = 0.f; acc3[i][j][r] = 0.f; }

    const int nIter = K / 32;           // 32, even
    load_stage(0, 0);
    load_stage(1, 32);
    CP_COMMIT();
    for (int i = 0; i < nIter; i += 2) {
        CP_WAIT0();
        __syncthreads();
        if (i + 2 < nIter) {
            load_stage((i + 2) & 3, (i + 2) * 32);
            load_stage((i + 3) & 3, (i + 3) * 32);
            CP_COMMIT();
        }
#pragma unroll 1
        for (int u = 0; u < 2; u++) {
            uint32_t sb = sb0 + (uint32_t)((i + u) & 3) * G1_STG * 2;
#pragma unroll
            for (int ks = 0; ks < 2; ks++) {
                uint32_t koA = (uint32_t)ks * 32;
                uint32_t koB = (uint32_t)ks * ksB;
                uint32_t ah[4][4];
#pragma unroll
                for (int mi = 0; mi < 4; mi++)
                    LDSM4(ah[mi], sb + aOff[mi] + koA);
                uint32_t b1[4], b3[4];
                LDSM4T(b1, sb + b1OffT + koB);
                LDSM4T(b3, sb + b3OffT + koB);
#pragma unroll
                for (int mi = 0; mi < 4; mi++)
#pragma unroll
                    for (int nf = 0; nf < 2; nf++) {
                        mma_f16(acc1[mi][nf], ah[mi], b1[2*nf], b1[2*nf+1]);
                        mma_f16(acc3[mi][nf], ah[mi], b3[2*nf], b3[2*nf+1]);
                    }
            }
        }
    }

    int rr = lane >> 2, cc = (lane & 3) * 2;
#pragma unroll
    for (int mi = 0; mi < 4; mi++) {
        int gmb = rowBlock + wm * 64 + mi * 16 + rr;
#pragma unroll
        for (int nf = 0; nf < 2; nf++) {
            int col = colBlock + wn * 16 + nf * 8 + cc;
#pragma unroll
            for (int hf = 0; hf < 2; hf++) {
                int gm = gmb + hf * 8;
                if (gm < M) {
                    float v1a = acc1[mi][nf][hf*2], v1b = acc1[mi][nf][hf*2+1];
                    float v3a = acc3[mi][nf][hf*2], v3b = acc3[mi][nf][hf*2+1];
                    float h0 = v1a / (1.f + expf(-v1a)) * v3a;
                    float h1 = v1b / (1.f + expf(-v1b)) * v3b;
                    *reinterpret_cast<uint32_t*>(H + (size_t)gm * N + col) =
                        pack2(__float2half(h0), __float2half(h1));
                }
            }
        }
    }
}

// ---------------- GEMM2: down-proj (trans-B, BN=128, 4-stage pairs) -------------
#define G2_S_A   0
#define G2_S_B   5120
#define G2_STG   9472
#define G2_SMEM  (4 * G2_STG * 2)    // 75776 B

__global__ void __launch_bounds__(256, 2)
gemm2_kernel(float* __restrict__ out) {
    int z = blockIdx.z;
    bool sh = (z == NEXP);
    int M = sh ? TOK : g_cnt[z];
    int K = sh ? SHID : EHID;
    int rowBlock = blockIdx.y * 128;
    if (rowBlock >= M) return;
    int colBlock = blockIdx.x * 128;
    const fp16* A = sh ? g_hsh : g_hh + (size_t)z * TOK * EHID;
    const fp16* B = sh ? g_s2h : g_w2h + (size_t)z * EHID * DIM;
    float* Y      = sh ? out   : g_yp  + (size_t)z * TOK * DIM;

    extern __shared__ __align__(16) fp16 sm2[];
    uint32_t sb0 = smem_u32(sm2);

    int tid = threadIdx.x, lane = tid & 31, warp = tid >> 5;
    int wm = warp >> 2, wn = warp & 3;

    int ra = tid >> 1, ka = (tid & 1) * 16;
    bool aval = (rowBlock + ra) < M;
    const fp16* aph = A + (size_t)(aval ? rowBlock + ra : 0) * K + ka;
    uint32_t adst = (uint32_t)(ra * LDH + ka) * 2;

    int brow = tid >> 3, bch = (tid & 7) * 8;
    const fp16* bp = B + (size_t)brow * DIM + colBlock + bch;
    uint32_t bdst = (uint32_t)(G2_S_B + brow * LDB2 + bch) * 2;

    auto load_stage = [&](int s, int k0) {
        uint32_t sb = sb0 + (uint32_t)s * G2_STG * 2;
        cp16(sb + G2_S_A * 2 + adst,      aph + k0,     aval);
        cp16(sb + G2_S_A * 2 + adst + 16, aph + k0 + 8, aval);
        size_t ko = (size_t)k0 * DIM;
        cp16(sb + bdst,       bp + ko,      true);
        cp16(sb + bdst + 128, bp + ko + 64, true);
    };

    int lrow = lane & 15, lkA = (lane >> 4) * 8;
    uint32_t aOff[4];
#pragma unroll
    for (int mi = 0; mi < 4; mi++) {
        int r = wm * 64 + mi * 16 + lrow;
        aOff[mi] = (uint32_t)(G2_S_A + r * LDH + lkA) * 2;
    }
    int bg = lane >> 3, br = lane & 7;
    uint32_t bOffT[2];
#pragma unroll
    for (int ng = 0; ng < 2; ng++) {
        int n = wn * 32 + ng * 16 + (bg >> 1) * 8;
        bOffT[ng] = (uint32_t)(G2_S_B + ((bg & 1) * 8 + br) * LDB2 + n) * 2;
    }
    const uint32_t ksB = 16 * LDB2 * 2;

    float acc[4][4][4];
#pragma unroll
    for (int i = 0; i < 4; i++)
#pragma unroll
        for (int j = 0; j < 4; j++)
#pragma unroll
            for (int r = 0; r < 4; r++) acc[i][j][r] = 0.f;

    const int nIter = K / 32;           // 88 or 48, even
    load_stage(0, 0);
    load_stage(1, 32);
    CP_COMMIT();
    for (int i = 0; i < nIter; i += 2) {
        CP_WAIT0();
        __syncthreads();
        if (i + 2 < nIter) {
            load_stage((i + 2) & 3, (i + 2) * 32);
            load_stage((i + 3) & 3, (i + 3) * 32);
            CP_COMMIT();
        }
#pragma unroll 1
        for (int u = 0; u < 2; u++) {
            uint32_t sb = sb0 + (uint32_t)((i + u) & 3) * G2_STG * 2;
#pragma unroll
            for (int ks = 0; ks < 2; ks++) {
                uint32_t koA = (uint32_t)ks * 32;
                uint32_t koB = (uint32_t)ks * ksB;
                uint32_t ah[4][4];
#pragma unroll
                for (int mi = 0; mi < 4; mi++)
                    LDSM4(ah[mi], sb + aOff[mi] + koA);
                uint32_t b[2][4];
#pragma unroll
                for (int ng = 0; ng < 2; ng++)
                    LDSM4T(b[ng], sb + bOffT[ng] + koB);
#pragma unroll
                for (int mi = 0; mi < 4; mi++)
#pragma unroll
                    for (int nf = 0; nf < 4; nf++)
                        mma_f16(acc[mi][nf], ah[mi], b[nf >> 1][(nf & 1) * 2],
                                b[nf >> 1][(nf & 1) * 2 + 1]);
            }
        }
    }

    int rr = lane >> 2, cc = (lane & 3) * 2;
#pragma unroll
    for (int mi = 0; mi < 4; mi++) {
        int gmb = rowBlock + wm * 64 + mi * 16 + rr;
#pragma unroll
        for (int hf = 0; hf < 2; hf++) {
            int gm = gmb + hf * 8;
            if (gm < M) {
                float w = sh ? 1.0f : g_wgt[z * TOK + gm];
                float* dst = Y + (size_t)gm * DIM;
#pragma unroll
                for (int nf = 0; nf < 4; nf++) {
                    int col = colBlock + wn * 32 + nf * 8 + cc;
                    float2 v;
                    v.x = w * acc[mi][nf][hf*2];
                    v.y = w * acc[mi][nf][hf*2+1];
                    *reinterpret_cast<float2*>(dst + col) = v;
                }
            }
        }
    }
}

// out[t] += yp[slot0(t)] + yp[slot1(t)]; also re-zeroes g_cnt for the next call
__global__ void combine_kernel(float* __restrict__ out) {
    int t = blockIdx.x;
    int d = threadIdx.x;
    if (t == 0 && d < NEXP) g_cnt[d] = 0;
    int s0 = g_slot[2 * t], s1 = g_slot[2 * t + 1];
    float4* o = reinterpret_cast<float4*>(out) + (size_t)t * 256 + d;
    const float4 a  = *o;
    const float4 b0 = reinterpret_cast<const float4*>(g_yp)[(size_t)s0 * 256 + d];
    const float4 b1 = reinterpret_cast<const float4*>(g_yp)[(size_t)s1 * 256 + d];
    float4 r;
    r.x = a.x + (b0.x + b1.x);
    r.y = a.y + (b0.y + b1.y);
    r.z = a.z + (b0.z + b1.z);
    r.w = a.w + (b0.w + b1.w);
    *o = r;
}

// ---------------- launcher -----------------------------------------------------
extern "C" void kernel_launch(void* const* d_in, const int* in_sizes, int n_in,
                              void* d_out, int out_size) {
    const float* x   = (const float*)d_in[0];
    const float* gw  = (const float*)d_in[1];
    const float* w1  = (const float*)d_in[2];
    const float* w2  = (const float*)d_in[3];
    const float* w3  = (const float*)d_in[4];
    const float* sw1 = (const float*)d_in[5];
    const float* sw2 = (const float*)d_in[6];
    const float* sw3 = (const float*)d_in[7];
    float* out = (float*)d_out;
    (void)in_sizes; (void)n_in; (void)out_size;

    cudaFuncSetAttribute(gemm1_kernel, cudaFuncAttributeMaxDynamicSharedMemorySize, G1_SMEM);
    cudaFuncSetAttribute(gemm2_kernel, cudaFuncAttributeMaxDynamicSharedMemorySize, G2_SMEM);

    // streaming weight conversion (no transpose) + gate/top-2 + x fp16 copy
    cvt_all_kernel<<<C_GATE, 256>>>(w1, w3, w2, sw1, sw3, sw2, x, gw);

    // merged up-proj: z<8 routed experts, z==8 shared expert
    gemm1_kernel<<<dim3(EHID / 64, TOK / 128, NEXP + 1), 256, G1_SMEM>>>();
    // merged down-proj: shared writes d_out, routed writes yp partials
    gemm2_kernel<<<dim3(DIM / 128, TOK / 128, NEXP + 1), 256, G2_SMEM>>>(out);

    // combine (+ reset g_cnt for next call)
    combine_kernel<<<TOK, 256>>>(out);
}

// round 17
// speedup vs baseline: 1.4927x; 1.0181x over previous
#include <cuda_runtime.h>
#include <cuda_fp16.h>
#include <math.h>
#include <stdint.h>

#define TOK   4096
#define DIM   1024
#define NEXP  8
#define EHID  2816
#define SHID  1536
#define LDH   40      // A-tile smem row stride (halves): 32 data + 8 pad
#define LDB1  72      // gemm1 B-tile row stride (halves): 64 data + 8 pad
#define LDB2  136     // gemm2 B-tile row stride (halves): 128 data + 8 pad

typedef __half fp16;

// ---------------- scratch (device globals; zero-initialized at load) ---------
__device__ fp16  g_xh [(size_t)TOK*DIM];
__device__ fp16  g_w1h[(size_t)NEXP*DIM*EHID];   // native [e][K=DIM][N=EHID]
__device__ fp16  g_w3h[(size_t)NEXP*DIM*EHID];
__device__ fp16  g_w2h[(size_t)NEXP*EHID*DIM];   // native [e][K=EHID][N=DIM]
__device__ fp16  g_s1h[(size_t)DIM*SHID];
__device__ fp16  g_s3h[(size_t)DIM*SHID];
__device__ fp16  g_s2h[(size_t)SHID*DIM];
__device__ fp16  g_hh [(size_t)NEXP*TOK*EHID];
__device__ fp16  g_hsh[(size_t)TOK*SHID];
__device__ float g_yp [(size_t)NEXP*TOK*DIM];
__device__ int   g_cnt[NEXP];                    // zeroed by combine_kernel tail
__device__ int   g_idx[NEXP*TOK];
__device__ float g_wgt[NEXP*TOK];
__device__ int   g_slot[TOK*2];

// ---------------- helpers ----------------------------------------------------
__device__ __forceinline__ uint32_t smem_u32(const void* p) {
    uint32_t a;
    asm("{ .reg .u64 t; cvta.to.shared.u64 t, %1; cvt.u32.u64 %0, t; }"
        : "=r"(a) : "l"(p));
    return a;
}
__device__ __forceinline__ void cp16(uint32_t saddr, const void* g, bool valid) {
    int sz = valid ? 16 : 0;
    asm volatile("cp.async.cg.shared.global [%0], [%1], 16, %2;"
                 :: "r"(saddr), "l"(g), "r"(sz));
}
#define CP_COMMIT() asm volatile("cp.async.commit_group;")
#define CP_WAIT0()  asm volatile("cp.async.wait_group 0;")

#define LDSM4(r, addr) \
    asm volatile("ldmatrix.sync.aligned.m8n8.x4.shared.b16 {%0,%1,%2,%3}, [%4];" \
        : "=r"((r)[0]), "=r"((r)[1]), "=r"((r)[2]), "=r"((r)[3]) : "r"(addr))

#define LDSM4T(r, addr) \
    asm volatile("ldmatrix.sync.aligned.m8n8.x4.trans.shared.b16 {%0,%1,%2,%3}, [%4];" \
        : "=r"((r)[0]), "=r"((r)[1]), "=r"((r)[2]), "=r"((r)[3]) : "r"(addr))

__device__ __forceinline__ void mma_f16(float d[4], const uint32_t a[4],
                                        uint32_t b0, uint32_t b1) {
    asm volatile(
        "mma.sync.aligned.m16n8k16.row.col.f32.f16.f16.f32 "
        "{%0,%1,%2,%3},{%4,%5,%6,%7},{%8,%9},{%0,%1,%2,%3};"
        : "+f"(d[0]), "+f"(d[1]), "+f"(d[2]), "+f"(d[3])
        : "r"(a[0]), "r"(a[1]), "r"(a[2]), "r"(a[3]), "r"(b0), "r"(b1));
}

__device__ __forceinline__ uint32_t pack2(fp16 a, fp16 b) {
    return ((uint32_t)__half_as_ushort(b) << 16) | (uint32_t)__half_as_ushort(a);
}

// ---------------- streaming conversions + gate (one launch) --------------------
#define BW1  2816
#define BSH  192
#define C_W1 BW1
#define C_W3 (C_W1 + BW1)
#define C_W2 (C_W3 + BW1)
#define C_S1 (C_W2 + BSH)
#define C_S3 (C_S1 + BSH)
#define C_S2 (C_S3 + BSH)
#define C_GATE (C_S2 + TOK / 8)

__device__ __forceinline__ void cvt_seg(const float* __restrict__ in,
                                        fp16* __restrict__ out, int blk) {
    size_t base4 = (size_t)blk * 2048 + threadIdx.x;
    const float4* src = reinterpret_cast<const float4*>(in) + base4;
    uint2* dst = reinterpret_cast<uint2*>(out) + base4;
#pragma unroll
    for (int i = 0; i < 8; i++) {
        float4 v = src[(size_t)i * 256];
        uint2 o;
        o.x = pack2(__float2half(v.x), __float2half(v.y));
        o.y = pack2(__float2half(v.z), __float2half(v.w));
        dst[(size_t)i * 256] = o;
    }
}

__device__ __forceinline__ void gate_body(const float* __restrict__ x,
                                          const float* __restrict__ gw,
                                          int blk) {
    int tok  = blk * 8 + (threadIdx.x >> 5);
    int lane = threadIdx.x & 31;
    if (tok >= TOK) return;
    const float4* xr = reinterpret_cast<const float4*>(x + (size_t)tok * DIM);
    uint2* xo = reinterpret_cast<uint2*>(g_xh + (size_t)tok * DIM);
    float acc[NEXP];
#pragma unroll
    for (int e = 0; e < NEXP; e++) acc[e] = 0.f;
#pragma unroll
    for (int j = 0; j < 8; j++) {
        int q = lane + j * 32;
        float4 v = xr[q];
        uint2 ph;
        ph.x = pack2(__float2half(v.x), __float2half(v.y));
        ph.y = pack2(__float2half(v.z), __float2half(v.w));
        xo[q] = ph;
        int d = q * 4;
#pragma unroll
        for (int e = 0; e < NEXP; e++) {
            const float* gr = gw + e * DIM + d;
            acc[e] = fmaf(v.x, gr[0], acc[e]);
            acc[e] = fmaf(v.y, gr[1], acc[e]);
            acc[e] = fmaf(v.z, gr[2], acc[e]);
            acc[e] = fmaf(v.w, gr[3], acc[e]);
        }
    }
#pragma unroll
    for (int e = 0; e < NEXP; e++)
#pragma unroll
        for (int off = 16; off > 0; off >>= 1)
            acc[e] += __shfl_xor_sync(0xffffffffu, acc[e], off);
    if (lane == 0) {
        float mx = acc[0];
#pragma unroll
        for (int e = 1; e < NEXP; e++) mx = fmaxf(mx, acc[e]);
        float p[NEXP], s = 0.f;
#pragma unroll
        for (int e = 0; e < NEXP; e++) { p[e] = expf(acc[e] - mx); s += p[e]; }
        float inv = 1.f / s;
#pragma unroll
        for (int e = 0; e < NEXP; e++) p[e] *= inv;
        int i1 = 0;
#pragma unroll
        for (int e = 1; e < NEXP; e++) if (p[e] > p[i1]) i1 = e;
        int i2 = (i1 == 0) ? 1 : 0;
#pragma unroll
        for (int e = 0; e < NEXP; e++) if (e != i1 && p[e] > p[i2]) i2 = e;
        int pos1 = atomicAdd(&g_cnt[i1], 1);
        g_idx[i1 * TOK + pos1] = tok;  g_wgt[i1 * TOK + pos1] = p[i1];
        g_slot[2 * tok] = i1 * TOK + pos1;
        int pos2 = atomicAdd(&g_cnt[i2], 1);
        g_idx[i2 * TOK + pos2] = tok;  g_wgt[i2 * TOK + pos2] = p[i2];
        g_slot[2 * tok + 1] = i2 * TOK + pos2;
    }
}

__global__ void __launch_bounds__(256)
cvt_all_kernel(const float* __restrict__ w1, const float* __restrict__ w3,
               const float* __restrict__ w2, const float* __restrict__ sw1,
               const float* __restrict__ sw3, const float* __restrict__ sw2,
               const float* __restrict__ x,  const float* __restrict__ gw) {
    int t = blockIdx.x;
    if      (t < C_W1) cvt_seg(w1,  g_w1h, t);
    else if (t < C_W3) cvt_seg(w3,  g_w3h, t - C_W1);
    else if (t < C_W2) cvt_seg(w2,  g_w2h, t - C_W3);
    else if (t < C_S1) cvt_seg(sw1, g_s1h, t - C_W2);
    else if (t < C_S3) cvt_seg(sw3, g_s3h, t - C_S1);
    else if (t < C_S2) cvt_seg(sw2, g_s2h, t - C_S3);
    else               gate_body(x, gw, t - C_S2);
}

// ---------------- GEMM1: fused SwiGLU up-proj (512 thr, 16 warps 4m x 4n) -------
// CTA tile: BM=128, BN=64 per B-matrix, BK=32. Warp tile 32x16 per matrix.
#define G1_S_A   0
#define G1_S_B1  5120
#define G1_S_B3  7424
#define G1_STG   9728
#define G1_SMEM  (4 * G1_STG * 2)    // 77824 B

__global__ void __launch_bounds__(512, 2)
gemm1_kernel() {
    const int K = DIM;
    int z = blockIdx.z;
    bool sh = (z == NEXP);
    int M = sh ? TOK : g_cnt[z];
    int N = sh ? SHID : EHID;
    int rowBlock = blockIdx.y * 128;
    if (rowBlock >= M) return;
    int colBlock = blockIdx.x * 64;
    if (colBlock >= N) return;
    const fp16* B1 = sh ? g_s1h : g_w1h + (size_t)z * DIM * EHID;
    const fp16* B3 = sh ? g_s3h : g_w3h + (size_t)z * DIM * EHID;
    fp16* H        = sh ? g_hsh : g_hh  + (size_t)z * TOK * EHID;

    extern __shared__ __align__(16) fp16 sm1[];
    uint32_t sb0 = smem_u32(sm1);

    int tid = threadIdx.x, lane = tid & 31, warp = tid >> 5;
    int wm = warp >> 2, wn = warp & 3;

    // A load: one 16B chunk per thread (128 rows x 4 chunks = 512)
    int ra = tid >> 2, ca = (tid & 3) * 8;
    bool aval = (rowBlock + ra) < M;
    int asrc = aval ? (sh ? rowBlock + ra : g_idx[z * TOK + rowBlock + ra]) : 0;
    const fp16* aph = g_xh + (size_t)asrc * K + ca;
    uint32_t adst = (uint32_t)(ra * LDH + ca) * 2;

    // B load: threads 0-255 -> B1, 256-511 -> B3; 32 rows x 8 chunks each
    int bt = tid & 255;
    int brow = bt >> 3, bch = (bt & 7) * 8;
    const fp16* bp = ((tid < 256) ? B1 : B3) + (size_t)brow * N + colBlock + bch;
    uint32_t bdst = (uint32_t)(((tid < 256) ? G1_S_B1 : G1_S_B3)
                               + brow * LDB1 + bch) * 2;

    auto load_stage = [&](int s, int k0) {
        uint32_t sb = sb0 + (uint32_t)s * G1_STG * 2;
        cp16(sb + G1_S_A * 2 + adst, aph + k0, aval);
        cp16(sb + bdst, bp + (size_t)k0 * N, true);
    };

    int lrow = lane & 15, lkA = (lane >> 4) * 8;
    uint32_t aOff[2];
#pragma unroll
    for (int mi = 0; mi < 2; mi++) {
        int r = wm * 32 + mi * 16 + lrow;
        aOff[mi] = (uint32_t)(G1_S_A + r * LDH + lkA) * 2;
    }
    int bg = lane >> 3, br = lane & 7;
    uint32_t bRowT = (uint32_t)(((bg & 1) * 8 + br) * LDB1 + wn * 16 + (bg >> 1) * 8) * 2;
    uint32_t b1OffT = G1_S_B1 * 2 + bRowT;
    uint32_t b3OffT = G1_S_B3 * 2 + bRowT;
    const uint32_t ksB = 16 * LDB1 * 2;

    float acc1[2][2][4], acc3[2][2][4];
#pragma unroll
    for (int i = 0; i < 2; i++)
#pragma unroll
        for (int j = 0; j < 2; j++)
#pragma unroll
            for (int r = 0; r < 4; r++) { acc1[i][j][r] = 0.f; acc3[i][j][r] = 0.f; }

    const int nIter = K / 32;           // 32, even
    load_stage(0, 0);
    load_stage(1, 32);
    CP_COMMIT();
    for (int i = 0; i < nIter; i += 2) {
        CP_WAIT0();
        __syncthreads();
        if (i + 2 < nIter) {
            load_stage((i + 2) & 3, (i + 2) * 32);
            load_stage((i + 3) & 3, (i + 3) * 32);
            CP_COMMIT();
        }
#pragma unroll 1
        for (int u = 0; u < 2; u++) {
            uint32_t sb = sb0 + (uint32_t)((i + u) & 3) * G1_STG * 2;
#pragma unroll
            for (int ks = 0; ks < 2; ks++) {
                uint32_t koA = (uint32_t)ks * 32;
                uint32_t koB = (uint32_t)ks * ksB;
                uint32_t ah[2][4];
#pragma unroll
                for (int mi = 0; mi < 2; mi++)
                    LDSM4(ah[mi], sb + aOff[mi] + koA);
                uint32_t b1[4], b3[4];
                LDSM4T(b1, sb + b1OffT + koB);
                LDSM4T(b3, sb + b3OffT + koB);
#pragma unroll
                for (int mi = 0; mi < 2; mi++)
#pragma unroll
                    for (int nf = 0; nf < 2; nf++) {
                        mma_f16(acc1[mi][nf], ah[mi], b1[2*nf], b1[2*nf+1]);
                        mma_f16(acc3[mi][nf], ah[mi], b3[2*nf], b3[2*nf+1]);
                    }
            }
        }
    }

    int rr = lane >> 2, cc = (lane & 3) * 2;
#pragma unroll
    for (int mi = 0; mi < 2; mi++) {
        int gmb = rowBlock + wm * 32 + mi * 16 + rr;
#pragma unroll
        for (int nf = 0; nf < 2; nf++) {
            int col = colBlock + wn * 16 + nf * 8 + cc;
#pragma unroll
            for (int hf = 0; hf < 2; hf++) {
                int gm = gmb + hf * 8;
                if (gm < M) {
                    float v1a = acc1[mi][nf][hf*2], v1b = acc1[mi][nf][hf*2+1];
                    float v3a = acc3[mi][nf][hf*2], v3b = acc3[mi][nf][hf*2+1];
                    float h0 = v1a / (1.f + expf(-v1a)) * v3a;
                    float h1 = v1b / (1.f + expf(-v1b)) * v3b;
                    *reinterpret_cast<uint32_t*>(H + (size_t)gm * N + col) =
                        pack2(__float2half(h0), __float2half(h1));
                }
            }
        }
    }
}

// ---------------- GEMM2: down-proj (512 thr, 16 warps 4m x 4n, BN=128) ----------
#define G2_S_A   0
#define G2_S_B   5120
#define G2_STG   9472
#define G2_SMEM  (4 * G2_STG * 2)    // 75776 B

__global__ void __launch_bounds__(512, 2)
gemm2_kernel(float* __restrict__ out) {
    int z = blockIdx.z;
    bool sh = (z == NEXP);
    int M = sh ? TOK : g_cnt[z];
    int K = sh ? SHID : EHID;
    int rowBlock = blockIdx.y * 128;
    if (rowBlock >= M) return;
    int colBlock = blockIdx.x * 128;
    const fp16* A = sh ? g_hsh : g_hh + (size_t)z * TOK * EHID;
    const fp16* B = sh ? g_s2h : g_w2h + (size_t)z * EHID * DIM;
    float* Y      = sh ? out   : g_yp  + (size_t)z * TOK * DIM;

    extern __shared__ __align__(16) fp16 sm2[];
    uint32_t sb0 = smem_u32(sm2);

    int tid = threadIdx.x, lane = tid & 31, warp = tid >> 5;
    int wm = warp >> 2, wn = warp & 3;

    // A: one 16B chunk per thread (128 rows x 4 chunks)
    int ra = tid >> 2, ca = (tid & 3) * 8;
    bool aval = (rowBlock + ra) < M;
    const fp16* aph = A + (size_t)(aval ? rowBlock + ra : 0) * K + ca;
    uint32_t adst = (uint32_t)(ra * LDH + ca) * 2;

    // B: one 16B chunk per thread (32 rows x 16 chunks)
    int brow = tid >> 4, bch = (tid & 15) * 8;
    const fp16* bp = B + (size_t)brow * DIM + colBlock + bch;
    uint32_t bdst = (uint32_t)(G2_S_B + brow * LDB2 + bch) * 2;

    auto load_stage = [&](int s, int k0) {
        uint32_t sb = sb0 + (uint32_t)s * G2_STG * 2;
        cp16(sb + G2_S_A * 2 + adst, aph + k0, aval);
        cp16(sb + bdst, bp + (size_t)k0 * DIM, true);
    };

    int lrow = lane & 15, lkA = (lane >> 4) * 8;
    uint32_t aOff[2];
#pragma unroll
    for (int mi = 0; mi < 2; mi++) {
        int r = wm * 32 + mi * 16 + lrow;
        aOff[mi] = (uint32_t)(G2_S_A + r * LDH + lkA) * 2;
    }
    int bg = lane >> 3, br = lane & 7;
    uint32_t bOffT[2];
#pragma unroll
    for (int ng = 0; ng < 2; ng++) {
        int n = wn * 32 + ng * 16 + (bg >> 1) * 8;
        bOffT[ng] = (uint32_t)(G2_S_B + ((bg & 1) * 8 + br) * LDB2 + n) * 2;
    }
    const uint32_t ksB = 16 * LDB2 * 2;

    float acc[2][4][4];
#pragma unroll
    for (int i = 0; i < 2; i++)
#pragma unroll
        for (int j = 0; j < 4; j++)
#pragma unroll
            for (int r = 0; r < 4; r++) acc[i][j][r] = 0.f;

    const int nIter = K / 32;           // 88 or 48, even
    load_stage(0, 0);
    load_stage(1, 32);
    CP_COMMIT();
    for (int i = 0; i < nIter; i += 2) {
        CP_WAIT0();
        __syncthreads();
        if (i + 2 < nIter) {
            load_stage((i + 2) & 3, (i + 2) * 32);
            load_stage((i + 3) & 3, (i + 3) * 32);
            CP_COMMIT();
        }
#pragma unroll 1
        for (int u = 0; u < 2; u++) {
            uint32_t sb = sb0 + (uint32_t)((i + u) & 3) * G2_STG * 2;
#pragma unroll
            for (int ks = 0; ks < 2; ks++) {
                uint32_t koA = (uint32_t)ks * 32;
                uint32_t koB = (uint32_t)ks * ksB;
                uint32_t ah[2][4];
#pragma unroll
                for (int mi = 0; mi < 2; mi++)
                    LDSM4(ah[mi], sb + aOff[mi] + koA);
                uint32_t b[2][4];
#pragma unroll
                for (int ng = 0; ng < 2; ng++)
                    LDSM4T(b[ng], sb + bOffT[ng] + koB);
#pragma unroll
                for (int mi = 0; mi < 2; mi++)
#pragma unroll
                    for (int nf = 0; nf < 4; nf++)
                        mma_f16(acc[mi][nf], ah[mi], b[nf >> 1][(nf & 1) * 2],
                                b[nf >> 1][(nf & 1) * 2 + 1]);
            }
        }
    }

    int rr = lane >> 2, cc = (lane & 3) * 2;
#pragma unroll
    for (int mi = 0; mi < 2; mi++) {
        int gmb = rowBlock + wm * 32 + mi * 16 + rr;
#pragma unroll
        for (int hf = 0; hf < 2; hf++) {
            int gm = gmb + hf * 8;
            if (gm < M) {
                float w = sh ? 1.0f : g_wgt[z * TOK + gm];
                float* dst = Y + (size_t)gm * DIM;
#pragma unroll
                for (int nf = 0; nf < 4; nf++) {
                    int col = colBlock + wn * 32 + nf * 8 + cc;
                    float2 v;
                    v.x = w * acc[mi][nf][hf*2];
                    v.y = w * acc[mi][nf][hf*2+1];
                    *reinterpret_cast<float2*>(dst + col) = v;
                }
            }
        }
    }
}

// out[t] += yp[slot0(t)] + yp[slot1(t)]; also re-zeroes g_cnt for the next call
__global__ void combine_kernel(float* __restrict__ out) {
    int t = blockIdx.x;
    int d = threadIdx.x;
    if (t == 0 && d < NEXP) g_cnt[d] = 0;
    int s0 = g_slot[2 * t], s1 = g_slot[2 * t + 1];
    float4* o = reinterpret_cast<float4*>(out) + (size_t)t * 256 + d;
    const float4 a  = *o;
    const float4 b0 = reinterpret_cast<const float4*>(g_yp)[(size_t)s0 * 256 + d];
    const float4 b1 = reinterpret_cast<const float4*>(g_yp)[(size_t)s1 * 256 + d];
    float4 r;
    r.x = a.x + (b0.x + b1.x);
    r.y = a.y + (b0.y + b1.y);
    r.z = a.z + (b0.z + b1.z);
    r.w = a.w + (b0.w + b1.w);
    *o = r;
}

// ---------------- launcher -----------------------------------------------------
extern "C" void kernel_launch(void* const* d_in, const int* in_sizes, int n_in,
                              void* d_out, int out_size) {
    const float* x   = (const float*)d_in[0];
    const float* gw  = (const float*)d_in[1];
    const float* w1  = (const float*)d_in[2];
    const float* w2  = (const float*)d_in[3];
    const float* w3  = (const float*)d_in[4];
    const float* sw1 = (const float*)d_in[5];
    const float* sw2 = (const float*)d_in[6];
    const float* sw3 = (const float*)d_in[7];
    float* out = (float*)d_out;
    (void)in_sizes; (void)n_in; (void)out_size;

    cudaFuncSetAttribute(gemm1_kernel, cudaFuncAttributeMaxDynamicSharedMemorySize, G1_SMEM);
    cudaFuncSetAttribute(gemm2_kernel, cudaFuncAttributeMaxDynamicSharedMemorySize, G2_SMEM);

    // streaming weight conversion (no transpose) + gate/top-2 + x fp16 copy
    cvt_all_kernel<<<C_GATE, 256>>>(w1, w3, w2, sw1, sw3, sw2, x, gw);

    // merged up-proj: z<8 routed experts, z==8 shared expert
    gemm1_kernel<<<dim3(EHID / 64, TOK / 128, NEXP + 1), 512, G1_SMEM>>>();
    // merged down-proj: shared writes d_out, routed writes yp partials
    gemm2_kernel<<<dim3(DIM / 128, TOK / 128, NEXP + 1), 512, G2_SMEM>>>(out);

    // combine (+ reset g_cnt for next call)
    combine_kernel<<<TOK, 256>>>(out);
}